// round 1
// baseline (speedup 1.0000x reference)
#include <cuda_runtime.h>
#include <math.h>

#define NROWS 8192
#define CDIM  512
#define EDIM  256

// ---------------- scratch (static device globals; no allocation) ----------------
__device__ float g_xe [NROWS * CDIM];           // x + enc@W_enc^T + b_enc
__device__ float g_xn [NROWS * CDIM];           // LN1(xe)
__device__ float g_h  [NROWS * CDIM];           // per-head h
__device__ float g_att[NROWS * CDIM];           // per-head LN2(attn_out + xe)
__device__ float g_s1 [NROWS];
__device__ float g_s2 [NROWS];
__device__ float g_sorted[NROWS];
__device__ int   g_perm  [NROWS];
__device__ float g_wpos  [NROWS];               // exp(s2_sorted)
__device__ float g_wneg  [NROWS];               // exp(0.01*s2_sorted)
__device__ float g_Apre[(NROWS + 1) * CDIM];    // prefix sums of wneg*h (sorted order)
__device__ float g_Asuf[(NROWS + 1) * CDIM];    // suffix sums of wpos*h
__device__ float g_Zpre[NROWS + 1];
__device__ float g_Zsuf[NROWS + 1];

// ---------------- GEMM: C = A(MxK) * B(NxK)^T, both row-major, k-contiguous ----
// modes: 0: C = acc
//        1: C = acc + addmat + bias[n]
//        2: C = elu(acc) * scale
//        3: C += elu(acc) * scale
__global__ __launch_bounds__(256)
void gemm_nt(const float* __restrict__ A, const float* __restrict__ B,
             float* __restrict__ Cmat, int M, int N, int K, int mode,
             const float* __restrict__ addmat, const float* __restrict__ bias,
             float scale)
{
    __shared__ float As[8][128];
    __shared__ float Bs[8][128];
    const int tid = threadIdx.x;
    const int tx = tid & 15;          // N direction (16)
    const int ty = tid >> 4;          // M direction (16)
    const int lrow = tid >> 1;        // 0..127
    const int lcol = (tid & 1) << 2;  // 0 or 4

    const float* Aptr = A + (size_t)(blockIdx.y * 128 + lrow) * K + lcol;
    const float* Bptr = B + (size_t)(blockIdx.x * 128 + lrow) * K + lcol;

    float acc[8][8];
#pragma unroll
    for (int i = 0; i < 8; i++)
#pragma unroll
        for (int j = 0; j < 8; j++) acc[i][j] = 0.f;

    for (int k0 = 0; k0 < K; k0 += 8) {
        float4 av = *(const float4*)(Aptr + k0);
        float4 bv = *(const float4*)(Bptr + k0);
        As[lcol + 0][lrow] = av.x; As[lcol + 1][lrow] = av.y;
        As[lcol + 2][lrow] = av.z; As[lcol + 3][lrow] = av.w;
        Bs[lcol + 0][lrow] = bv.x; Bs[lcol + 1][lrow] = bv.y;
        Bs[lcol + 2][lrow] = bv.z; Bs[lcol + 3][lrow] = bv.w;
        __syncthreads();
#pragma unroll
        for (int k = 0; k < 8; k++) {
            float a[8], b[8];
            float4 a0 = *(const float4*)&As[k][ty * 8];
            float4 a1 = *(const float4*)&As[k][ty * 8 + 4];
            float4 b0 = *(const float4*)&Bs[k][tx * 8];
            float4 b1 = *(const float4*)&Bs[k][tx * 8 + 4];
            a[0]=a0.x; a[1]=a0.y; a[2]=a0.z; a[3]=a0.w;
            a[4]=a1.x; a[5]=a1.y; a[6]=a1.z; a[7]=a1.w;
            b[0]=b0.x; b[1]=b0.y; b[2]=b0.z; b[3]=b0.w;
            b[4]=b1.x; b[5]=b1.y; b[6]=b1.z; b[7]=b1.w;
#pragma unroll
            for (int i = 0; i < 8; i++)
#pragma unroll
                for (int j = 0; j < 8; j++) acc[i][j] = fmaf(a[i], b[j], acc[i][j]);
        }
        __syncthreads();
    }

    const int m0 = blockIdx.y * 128 + ty * 8;
    const int n0 = blockIdx.x * 128 + tx * 8;
#pragma unroll
    for (int i = 0; i < 8; i++) {
#pragma unroll
        for (int j = 0; j < 8; j++) {
            float v = acc[i][j];
            size_t idx = (size_t)(m0 + i) * N + (n0 + j);
            if (mode == 1) {
                v += addmat[idx] + bias[n0 + j];
            } else if (mode >= 2) {
                v = (v > 0.f) ? v : expm1f(v);
                v *= scale;
                if (mode == 3) v += Cmat[idx];
            }
            Cmat[idx] = v;
        }
    }
}

// ---------------- row LayerNorm (512 cols, 128 threads/row) --------------------
__global__ __launch_bounds__(128)
void ln_kernel(const float* __restrict__ in, float* __restrict__ out,
               const float* __restrict__ g, const float* __restrict__ b)
{
    const int row = blockIdx.x;
    const float* x = in + (size_t)row * CDIM;
    float v[4];
    float s = 0.f, ss = 0.f;
#pragma unroll
    for (int t = 0; t < 4; t++) {
        v[t] = x[threadIdx.x + 128 * t];
        s += v[t]; ss += v[t] * v[t];
    }
    __shared__ float rs[4], rss[4];
#pragma unroll
    for (int o = 16; o; o >>= 1) {
        s  += __shfl_down_sync(0xffffffffu, s,  o);
        ss += __shfl_down_sync(0xffffffffu, ss, o);
    }
    if ((threadIdx.x & 31) == 0) { rs[threadIdx.x >> 5] = s; rss[threadIdx.x >> 5] = ss; }
    __syncthreads();
    float S  = rs[0] + rs[1] + rs[2] + rs[3];
    float SS = rss[0] + rss[1] + rss[2] + rss[3];
    float mu  = S * (1.f / CDIM);
    float var = SS * (1.f / CDIM) - mu * mu;
    float inv = rsqrtf(var + 1e-5f);
#pragma unroll
    for (int t = 0; t < 4; t++) {
        int c = threadIdx.x + 128 * t;
        out[(size_t)row * CDIM + c] = (v[t] - mu) * inv * g[c] + b[c];
    }
}

// ---------------- s1/s2: per-row dot products against Wa -----------------------
__global__ void s_kernel(const float* __restrict__ h, const float* __restrict__ wa)
{
    const int row = blockIdx.x * 8 + threadIdx.y;
    const int lane = threadIdx.x;
    const float* hr = h + (size_t)row * CDIM;
    float a = 0.f, bv = 0.f;
#pragma unroll
    for (int t = 0; t < 16; t++) {
        int c = lane + 32 * t;
        float hv = hr[c];
        a  = fmaf(hv, wa[c], a);
        bv = fmaf(hv, wa[CDIM + c], bv);
    }
#pragma unroll
    for (int o = 16; o; o >>= 1) {
        a  += __shfl_down_sync(0xffffffffu, a,  o);
        bv += __shfl_down_sync(0xffffffffu, bv, o);
    }
    if (lane == 0) { g_s1[row] = a; g_s2[row] = bv; }
}

// ---------------- sort s2 by O(n^2) ranking (8192 elems, smem broadcast) -------
__global__ __launch_bounds__(256)
void rank_kernel()
{
    __shared__ float sh[NROWS];
    for (int t = threadIdx.x; t < NROWS; t += 256) sh[t] = g_s2[t];
    __syncthreads();
    const int i = blockIdx.x * 256 + threadIdx.x;
    const float v = sh[i];
    int r = 0;
#pragma unroll 8
    for (int j = 0; j < NROWS; j++) {
        float u = sh[j];
        r += (u < v) || (u == v && j < i);
    }
    g_sorted[r] = v;
    g_perm[r]   = i;
    g_wpos[r]   = expf(v);
    g_wneg[r]   = expf(0.01f * v);
}

// ---------------- prefix/suffix scans of weighted h rows -----------------------
// blocks 0..3: prefix (neg branch) over 128-col slices
// blocks 4..7: suffix (pos branch)
// block  8   : scalar Z scans
__global__ __launch_bounds__(128)
void scan_kernel()
{
    const int b = blockIdx.x;
    if (b < 4) {
        const int col = b * 128 + threadIdx.x;
        float acc = 0.f;
        g_Apre[col] = 0.f;
        for (int u = 0; u < NROWS; u++) {
            int r = g_perm[u];
            acc = fmaf(g_wneg[u], g_h[(size_t)r * CDIM + col], acc);
            g_Apre[(size_t)(u + 1) * CDIM + col] = acc;
        }
    } else if (b < 8) {
        const int col = (b - 4) * 128 + threadIdx.x;
        float acc = 0.f;
        g_Asuf[(size_t)NROWS * CDIM + col] = 0.f;
        for (int u = NROWS - 1; u >= 0; u--) {
            int r = g_perm[u];
            acc = fmaf(g_wpos[u], g_h[(size_t)r * CDIM + col], acc);
            g_Asuf[(size_t)u * CDIM + col] = acc;
        }
    } else {
        if (threadIdx.x == 0) {
            float acc = 0.f; g_Zpre[0] = 0.f;
            for (int u = 0; u < NROWS; u++) { acc += g_wneg[u]; g_Zpre[u + 1] = acc; }
        } else if (threadIdx.x == 1) {
            float acc = 0.f; g_Zsuf[NROWS] = 0.f;
            for (int u = NROWS - 1; u >= 0; u--) { acc += g_wpos[u]; g_Zsuf[u] = acc; }
        }
    }
}

// ---------------- per-row combine + residual + LN2 -----------------------------
__global__ __launch_bounds__(128)
void combine_kernel(const float* __restrict__ ln2g, const float* __restrict__ ln2b)
{
    const int row = blockIdx.x;
    __shared__ int sk;
    __shared__ float rs[4], rss[4];
    if (threadIdx.x == 0) {
        float thr = -g_s1[row];
        int lo = 0, hi = NROWS;
        while (lo < hi) {                      // first index with sorted > thr
            int mid = (lo + hi) >> 1;
            if (g_sorted[mid] <= thr) lo = mid + 1; else hi = mid;
        }
        sk = lo;
    }
    __syncthreads();
    const int k = sk;
    const float s1v = g_s1[row];
    const float ap = expf(s1v);
    const float an = expf(0.01f * s1v);
    const float den = ap * g_Zsuf[k] + an * g_Zpre[k];
    const float inv_den = 1.f / den;

    float v[4]; float s = 0.f, ss = 0.f;
#pragma unroll
    for (int t = 0; t < 4; t++) {
        int c = threadIdx.x + 128 * t;
        float num = ap * g_Asuf[(size_t)k * CDIM + c] + an * g_Apre[(size_t)k * CDIM + c];
        float val = num * inv_den + g_xe[(size_t)row * CDIM + c];
        v[t] = val; s += val; ss += val * val;
    }
#pragma unroll
    for (int o = 16; o; o >>= 1) {
        s  += __shfl_down_sync(0xffffffffu, s,  o);
        ss += __shfl_down_sync(0xffffffffu, ss, o);
    }
    if ((threadIdx.x & 31) == 0) { rs[threadIdx.x >> 5] = s; rss[threadIdx.x >> 5] = ss; }
    __syncthreads();
    float S  = rs[0] + rs[1] + rs[2] + rs[3];
    float SS = rss[0] + rss[1] + rss[2] + rss[3];
    float mu  = S * (1.f / CDIM);
    float var = SS * (1.f / CDIM) - mu * mu;
    float inv = rsqrtf(var + 1e-5f);
#pragma unroll
    for (int t = 0; t < 4; t++) {
        int c = threadIdx.x + 128 * t;
        g_att[(size_t)row * CDIM + c] = (v[t] - mu) * inv * ln2g[c] + ln2b[c];
    }
}

// ---------------- launch --------------------------------------------------------
extern "C" void kernel_launch(void* const* d_in, const int* in_sizes, int n_in,
                              void* d_out, int out_size)
{
    const float* x     = (const float*)d_in[0];
    const float* enc   = (const float*)d_in[1];
    const float* W_enc = (const float*)d_in[2];
    const float* b_enc = (const float*)d_in[3];
    const float* ln1g  = (const float*)d_in[4];
    const float* ln1b  = (const float*)d_in[5];
    const float* ln2g  = (const float*)d_in[6];
    const float* ln2b  = (const float*)d_in[7];
    const float* W0    = (const float*)d_in[8];
    const float* W1    = (const float*)d_in[9];
    const float* Wa    = (const float*)d_in[10];
    float* out = (float*)d_out;

    void *p_xe, *p_xn, *p_h, *p_att;
    cudaGetSymbolAddress(&p_xe,  g_xe);
    cudaGetSymbolAddress(&p_xn,  g_xn);
    cudaGetSymbolAddress(&p_h,   g_h);
    cudaGetSymbolAddress(&p_att, g_att);
    float* xe  = (float*)p_xe;
    float* xn  = (float*)p_xn;
    float* h   = (float*)p_h;
    float* att = (float*)p_att;

    dim3 gemm_grid(CDIM / 128, NROWS / 128);   // (4, 64)
    dim3 gemm_blk(256);

    // 1) xe = x + enc @ W_enc^T + b_enc
    gemm_nt<<<gemm_grid, gemm_blk>>>(enc, W_enc, xe, NROWS, CDIM, EDIM, 1, x, b_enc, 1.f);
    // 2) xn = LN1(xe)
    ln_kernel<<<NROWS, 128>>>(xe, xn, ln1g, ln1b);

    for (int head = 0; head < 2; head++) {
        const float* W0h = W0 + (size_t)head * CDIM * CDIM;
        const float* W1h = W1 + (size_t)head * CDIM * CDIM;
        const float* Wah = Wa + (size_t)head * 2 * CDIM;

        // 3) h = xn @ W0h^T
        gemm_nt<<<gemm_grid, gemm_blk>>>(xn, W0h, h, NROWS, CDIM, CDIM, 0, nullptr, nullptr, 1.f);
        // 4) s1, s2
        s_kernel<<<NROWS / 8, dim3(32, 8)>>>(h, Wah);
        // 5) sort s2 (rank), exp weights
        rank_kernel<<<NROWS / 256, 256>>>();
        // 6) prefix/suffix scans
        scan_kernel<<<9, 128>>>();
        // 7) combine + residual + LN2
        combine_kernel<<<NROWS, 128>>>(ln2g, ln2b);
        // 8) out (+)= elu(att @ W1h^T) / 2
        gemm_nt<<<gemm_grid, gemm_blk>>>(att, W1h, out, NROWS, CDIM, CDIM,
                                         head == 0 ? 2 : 3, nullptr, nullptr, 0.5f);
    }
}

// round 2
// speedup vs baseline: 4.3865x; 4.3865x over previous
#include <cuda_runtime.h>
#include <math.h>

#define NROWS 8192
#define CDIM  512
#define EDIM  256
#define CHUNK 128
#define NCHUNK (NROWS / CHUNK)   // 64

// ---------------- scratch (static device globals; no allocation) ----------------
__device__ float g_xe [NROWS * CDIM];           // x + enc@W_enc^T + b_enc
__device__ float g_xn [NROWS * CDIM];           // LN1(xe)
__device__ float g_h  [NROWS * CDIM];           // per-head h
__device__ float g_att[NROWS * CDIM];           // per-head LN2(attn_out + xe)
__device__ float g_s1 [NROWS];
__device__ float g_s2 [NROWS];
__device__ float g_sorted[NROWS];
__device__ int   g_perm  [NROWS];
__device__ float g_wpos  [NROWS];               // exp(s2_sorted)
__device__ float g_wneg  [NROWS];               // exp(0.01*s2_sorted)
__device__ float g_Apre[(NROWS + 1) * CDIM];    // prefix sums of wneg*h (sorted order)
__device__ float g_Asuf[(NROWS + 1) * CDIM];    // suffix sums of wpos*h
__device__ float g_Zpre[NROWS + 1];
__device__ float g_Zsuf[NROWS + 1];
// chunked-scan intermediates
__device__ float g_cpos[NCHUNK * CDIM];         // per-chunk totals (pos branch)
__device__ float g_cneg[NCHUNK * CDIM];
__device__ float g_offp[NCHUNK * CDIM];         // exclusive suffix offsets (pos)
__device__ float g_offn[NCHUNK * CDIM];         // exclusive prefix offsets (neg)
__device__ float g_zcp[NCHUNK], g_zcn[NCHUNK];
__device__ float g_zoffp[NCHUNK], g_zoffn[NCHUNK];

// ---------------- GEMM: C = A(MxK) * B(NxK)^T, both row-major, k-contiguous ----
// modes: 0: C = acc
//        1: C = acc + addmat + bias[n]
//        2: C = elu(acc) * scale
//        3: C += elu(acc) * scale
__global__ __launch_bounds__(256)
void gemm_nt(const float* __restrict__ A, const float* __restrict__ B,
             float* __restrict__ Cmat, int M, int N, int K, int mode,
             const float* __restrict__ addmat, const float* __restrict__ bias,
             float scale)
{
    __shared__ float As[8][128];
    __shared__ float Bs[8][128];
    const int tid = threadIdx.x;
    const int tx = tid & 15;          // N direction (16)
    const int ty = tid >> 4;          // M direction (16)
    const int lrow = tid >> 1;        // 0..127
    const int lcol = (tid & 1) << 2;  // 0 or 4

    const float* Aptr = A + (size_t)(blockIdx.y * 128 + lrow) * K + lcol;
    const float* Bptr = B + (size_t)(blockIdx.x * 128 + lrow) * K + lcol;

    float acc[8][8];
#pragma unroll
    for (int i = 0; i < 8; i++)
#pragma unroll
        for (int j = 0; j < 8; j++) acc[i][j] = 0.f;

    for (int k0 = 0; k0 < K; k0 += 8) {
        float4 av = *(const float4*)(Aptr + k0);
        float4 bv = *(const float4*)(Bptr + k0);
        As[lcol + 0][lrow] = av.x; As[lcol + 1][lrow] = av.y;
        As[lcol + 2][lrow] = av.z; As[lcol + 3][lrow] = av.w;
        Bs[lcol + 0][lrow] = bv.x; Bs[lcol + 1][lrow] = bv.y;
        Bs[lcol + 2][lrow] = bv.z; Bs[lcol + 3][lrow] = bv.w;
        __syncthreads();
#pragma unroll
        for (int k = 0; k < 8; k++) {
            float a[8], b[8];
            float4 a0 = *(const float4*)&As[k][ty * 8];
            float4 a1 = *(const float4*)&As[k][ty * 8 + 4];
            float4 b0 = *(const float4*)&Bs[k][tx * 8];
            float4 b1 = *(const float4*)&Bs[k][tx * 8 + 4];
            a[0]=a0.x; a[1]=a0.y; a[2]=a0.z; a[3]=a0.w;
            a[4]=a1.x; a[5]=a1.y; a[6]=a1.z; a[7]=a1.w;
            b[0]=b0.x; b[1]=b0.y; b[2]=b0.z; b[3]=b0.w;
            b[4]=b1.x; b[5]=b1.y; b[6]=b1.z; b[7]=b1.w;
#pragma unroll
            for (int i = 0; i < 8; i++)
#pragma unroll
                for (int j = 0; j < 8; j++) acc[i][j] = fmaf(a[i], b[j], acc[i][j]);
        }
        __syncthreads();
    }

    const int m0 = blockIdx.y * 128 + ty * 8;
    const int n0 = blockIdx.x * 128 + tx * 8;
#pragma unroll
    for (int i = 0; i < 8; i++) {
#pragma unroll
        for (int j = 0; j < 8; j++) {
            float v = acc[i][j];
            size_t idx = (size_t)(m0 + i) * N + (n0 + j);
            if (mode == 1) {
                v += addmat[idx] + bias[n0 + j];
            } else if (mode >= 2) {
                v = (v > 0.f) ? v : expm1f(v);
                v *= scale;
                if (mode == 3) v += Cmat[idx];
            }
            Cmat[idx] = v;
        }
    }
}

// ---------------- row LayerNorm (512 cols, 128 threads/row) --------------------
__global__ __launch_bounds__(128)
void ln_kernel(const float* __restrict__ in, float* __restrict__ out,
               const float* __restrict__ g, const float* __restrict__ b)
{
    const int row = blockIdx.x;
    const float* x = in + (size_t)row * CDIM;
    float v[4];
    float s = 0.f, ss = 0.f;
#pragma unroll
    for (int t = 0; t < 4; t++) {
        v[t] = x[threadIdx.x + 128 * t];
        s += v[t]; ss += v[t] * v[t];
    }
    __shared__ float rs[4], rss[4];
#pragma unroll
    for (int o = 16; o; o >>= 1) {
        s  += __shfl_down_sync(0xffffffffu, s,  o);
        ss += __shfl_down_sync(0xffffffffu, ss, o);
    }
    if ((threadIdx.x & 31) == 0) { rs[threadIdx.x >> 5] = s; rss[threadIdx.x >> 5] = ss; }
    __syncthreads();
    float S  = rs[0] + rs[1] + rs[2] + rs[3];
    float SS = rss[0] + rss[1] + rss[2] + rss[3];
    float mu  = S * (1.f / CDIM);
    float var = SS * (1.f / CDIM) - mu * mu;
    float inv = rsqrtf(var + 1e-5f);
#pragma unroll
    for (int t = 0; t < 4; t++) {
        int c = threadIdx.x + 128 * t;
        out[(size_t)row * CDIM + c] = (v[t] - mu) * inv * g[c] + b[c];
    }
}

// ---------------- s1/s2: per-row dot products against Wa -----------------------
__global__ void s_kernel(const float* __restrict__ h, const float* __restrict__ wa)
{
    const int row = blockIdx.x * 8 + threadIdx.y;
    const int lane = threadIdx.x;
    const float* hr = h + (size_t)row * CDIM;
    float a = 0.f, bv = 0.f;
#pragma unroll
    for (int t = 0; t < 16; t++) {
        int c = lane + 32 * t;
        float hv = hr[c];
        a  = fmaf(hv, wa[c], a);
        bv = fmaf(hv, wa[CDIM + c], bv);
    }
#pragma unroll
    for (int o = 16; o; o >>= 1) {
        a  += __shfl_down_sync(0xffffffffu, a,  o);
        bv += __shfl_down_sync(0xffffffffu, bv, o);
    }
    if (lane == 0) { g_s1[row] = a; g_s2[row] = bv; }
}

// ---------------- sort s2 by O(n^2) ranking (8192 elems, float4 smem sweep) ----
__global__ __launch_bounds__(256)
void rank_kernel()
{
    __shared__ float4 sh[NROWS / 4];
    for (int t = threadIdx.x; t < NROWS / 4; t += 256)
        sh[t] = ((const float4*)g_s2)[t];
    __syncthreads();
    const int i = blockIdx.x * 256 + threadIdx.x;
    const float v = g_s2[i];
    int r = 0;
#pragma unroll 4
    for (int jj = 0; jj < NROWS / 4; jj++) {
        float4 u = sh[jj];
        int j = jj * 4;
        r += (u.x < v) || (u.x == v && j + 0 < i);
        r += (u.y < v) || (u.y == v && j + 1 < i);
        r += (u.z < v) || (u.z == v && j + 2 < i);
        r += (u.w < v) || (u.w == v && j + 3 < i);
    }
    g_sorted[r] = v;
    g_perm[r]   = i;
    g_wpos[r]   = expf(v);
    g_wneg[r]   = expf(0.01f * v);
}

// ---------------- chunked parallel scan: phase 1 (per-chunk totals) ------------
// grid (4 col-slices, 64 chunks), 128 threads
__global__ __launch_bounds__(128)
void chunk_sum_kernel()
{
    const int s = blockIdx.x, c = blockIdx.y;
    const int col = s * 128 + threadIdx.x;
    const int u0 = c * CHUNK;
    float accp = 0.f, accn = 0.f;
    float zp = 0.f, zn = 0.f;
    const bool do_z = (s == 0 && threadIdx.x == 0);
#pragma unroll 4
    for (int t = 0; t < CHUNK; t++) {
        const int u = u0 + t;
        const int r = g_perm[u];
        const float wp = g_wpos[u], wn = g_wneg[u];
        const float hv = g_h[(size_t)r * CDIM + col];
        accp = fmaf(wp, hv, accp);
        accn = fmaf(wn, hv, accn);
        if (do_z) { zp += wp; zn += wn; }
    }
    g_cpos[c * CDIM + col] = accp;
    g_cneg[c * CDIM + col] = accn;
    if (do_z) { g_zcp[c] = zp; g_zcn[c] = zn; }
}

// ---------------- phase 2: scan the 64 chunk totals (1 block, 512 threads) -----
__global__ __launch_bounds__(512)
void chunk_scan_kernel()
{
    const int col = threadIdx.x;
    float run = 0.f;
    for (int c = 0; c < NCHUNK; c++) {             // exclusive prefix (neg)
        g_offn[c * CDIM + col] = run;
        run += g_cneg[c * CDIM + col];
    }
    run = 0.f;
    for (int c = NCHUNK - 1; c >= 0; c--) {        // exclusive suffix (pos)
        g_offp[c * CDIM + col] = run;
        run += g_cpos[c * CDIM + col];
    }
    if (col == 0) {
        float zr = 0.f;
        for (int c = 0; c < NCHUNK; c++) { g_zoffn[c] = zr; zr += g_zcn[c]; }
    } else if (col == 1) {
        float zr = 0.f;
        for (int c = NCHUNK - 1; c >= 0; c--) { g_zoffp[c] = zr; zr += g_zcp[c]; }
    }
}

// ---------------- phase 3: write full prefix/suffix arrays ---------------------
// grid (4 col-slices, 64 chunks), 128 threads
__global__ __launch_bounds__(128)
void scan_write_kernel()
{
    const int s = blockIdx.x, c = blockIdx.y;
    const int col = s * 128 + threadIdx.x;
    const int u0 = c * CHUNK;

    float accn    = g_offn[c * CDIM + col];
    const float base_suf = g_offp[c * CDIM + col] + g_cpos[c * CDIM + col];
    float pp = 0.f;

    const bool do_z = (s == 0 && threadIdx.x == 0);
    float zn = 0.f, zbs = 0.f, zpp = 0.f;
    if (do_z) { zn = g_zoffn[c]; zbs = g_zoffp[c] + g_zcp[c]; }

    if (c == 0) {
        g_Apre[col] = 0.f;
        if (do_z) g_Zpre[0] = 0.f;
    }
    if (c == NCHUNK - 1) {
        g_Asuf[(size_t)NROWS * CDIM + col] = 0.f;
        if (do_z) g_Zsuf[NROWS] = 0.f;
    }

#pragma unroll 4
    for (int t = 0; t < CHUNK; t++) {
        const int u = u0 + t;
        const int r = g_perm[u];
        const float wp = g_wpos[u], wn = g_wneg[u];
        const float hv = g_h[(size_t)r * CDIM + col];
        g_Asuf[(size_t)u * CDIM + col] = base_suf - pp;   // sum over v >= u
        pp   = fmaf(wp, hv, pp);
        accn = fmaf(wn, hv, accn);
        g_Apre[(size_t)(u + 1) * CDIM + col] = accn;      // sum over v <= u
        if (do_z) {
            g_Zsuf[u] = zbs - zpp;
            zpp += wp;
            zn  += wn;
            g_Zpre[u + 1] = zn;
        }
    }
}

// ---------------- per-row combine + residual + LN2 -----------------------------
__global__ __launch_bounds__(128)
void combine_kernel(const float* __restrict__ ln2g, const float* __restrict__ ln2b)
{
    const int row = blockIdx.x;
    __shared__ int sk;
    __shared__ float rs[4], rss[4];
    if (threadIdx.x == 0) {
        float thr = -g_s1[row];
        int lo = 0, hi = NROWS;
        while (lo < hi) {                      // first index with sorted > thr
            int mid = (lo + hi) >> 1;
            if (g_sorted[mid] <= thr) lo = mid + 1; else hi = mid;
        }
        sk = lo;
    }
    __syncthreads();
    const int k = sk;
    const float s1v = g_s1[row];
    const float ap = expf(s1v);
    const float an = expf(0.01f * s1v);
    const float den = ap * g_Zsuf[k] + an * g_Zpre[k];
    const float inv_den = 1.f / den;

    float v[4]; float s = 0.f, ss = 0.f;
#pragma unroll
    for (int t = 0; t < 4; t++) {
        int c = threadIdx.x + 128 * t;
        float num = ap * g_Asuf[(size_t)k * CDIM + c] + an * g_Apre[(size_t)k * CDIM + c];
        float val = num * inv_den + g_xe[(size_t)row * CDIM + c];
        v[t] = val; s += val; ss += val * val;
    }
#pragma unroll
    for (int o = 16; o; o >>= 1) {
        s  += __shfl_down_sync(0xffffffffu, s,  o);
        ss += __shfl_down_sync(0xffffffffu, ss, o);
    }
    if ((threadIdx.x & 31) == 0) { rs[threadIdx.x >> 5] = s; rss[threadIdx.x >> 5] = ss; }
    __syncthreads();
    float S  = rs[0] + rs[1] + rs[2] + rs[3];
    float SS = rss[0] + rss[1] + rss[2] + rss[3];
    float mu  = S * (1.f / CDIM);
    float var = SS * (1.f / CDIM) - mu * mu;
    float inv = rsqrtf(var + 1e-5f);
#pragma unroll
    for (int t = 0; t < 4; t++) {
        int c = threadIdx.x + 128 * t;
        g_att[(size_t)row * CDIM + c] = (v[t] - mu) * inv * ln2g[c] + ln2b[c];
    }
}

// ---------------- launch --------------------------------------------------------
extern "C" void kernel_launch(void* const* d_in, const int* in_sizes, int n_in,
                              void* d_out, int out_size)
{
    const float* x     = (const float*)d_in[0];
    const float* enc   = (const float*)d_in[1];
    const float* W_enc = (const float*)d_in[2];
    const float* b_enc = (const float*)d_in[3];
    const float* ln1g  = (const float*)d_in[4];
    const float* ln1b  = (const float*)d_in[5];
    const float* ln2g  = (const float*)d_in[6];
    const float* ln2b  = (const float*)d_in[7];
    const float* W0    = (const float*)d_in[8];
    const float* W1    = (const float*)d_in[9];
    const float* Wa    = (const float*)d_in[10];
    float* out = (float*)d_out;

    void *p_xe, *p_xn, *p_h, *p_att;
    cudaGetSymbolAddress(&p_xe,  g_xe);
    cudaGetSymbolAddress(&p_xn,  g_xn);
    cudaGetSymbolAddress(&p_h,   g_h);
    cudaGetSymbolAddress(&p_att, g_att);
    float* xe  = (float*)p_xe;
    float* xn  = (float*)p_xn;
    float* h   = (float*)p_h;
    float* att = (float*)p_att;

    dim3 gemm_grid(CDIM / 128, NROWS / 128);   // (4, 64)
    dim3 gemm_blk(256);
    dim3 scan_grid(CDIM / 128, NCHUNK);        // (4, 64)

    // 1) xe = x + enc @ W_enc^T + b_enc
    gemm_nt<<<gemm_grid, gemm_blk>>>(enc, W_enc, xe, NROWS, CDIM, EDIM, 1, x, b_enc, 1.f);
    // 2) xn = LN1(xe)
    ln_kernel<<<NROWS, 128>>>(xe, xn, ln1g, ln1b);

    for (int head = 0; head < 2; head++) {
        const float* W0h = W0 + (size_t)head * CDIM * CDIM;
        const float* W1h = W1 + (size_t)head * CDIM * CDIM;
        const float* Wah = Wa + (size_t)head * 2 * CDIM;

        // 3) h = xn @ W0h^T
        gemm_nt<<<gemm_grid, gemm_blk>>>(xn, W0h, h, NROWS, CDIM, CDIM, 0, nullptr, nullptr, 1.f);
        // 4) s1, s2
        s_kernel<<<NROWS / 8, dim3(32, 8)>>>(h, Wah);
        // 5) sort s2 (rank), exp weights
        rank_kernel<<<NROWS / 256, 256>>>();
        // 6) chunked parallel prefix/suffix scans
        chunk_sum_kernel<<<scan_grid, 128>>>();
        chunk_scan_kernel<<<1, 512>>>();
        scan_write_kernel<<<scan_grid, 128>>>();
        // 7) combine + residual + LN2
        combine_kernel<<<NROWS, 128>>>(ln2g, ln2b);
        // 8) out (+)= elu(att @ W1h^T) / 2
        gemm_nt<<<gemm_grid, gemm_blk>>>(att, W1h, out, NROWS, CDIM, CDIM,
                                         head == 0 ? 2 : 3, nullptr, nullptr, 0.5f);
    }
}

// round 4
// speedup vs baseline: 6.4440x; 1.4690x over previous
#include <cuda_runtime.h>
#include <cuda_bf16.h>
#include <math.h>
#include <stdint.h>

#define NROWS 8192
#define CDIM  512
#define EDIM  256
#define CHUNK 128
#define NCHUNK (NROWS / CHUNK)   // 64

// ================= helpers =================
__device__ __forceinline__ uint32_t smem_u32(const void* p) {
    uint32_t a;
    asm("{ .reg .u64 t; cvta.to.shared.u64 t, %1; cvt.u32.u64 %0, t; }" : "=r"(a) : "l"(p));
    return a;
}
#define CP_ASYNC(dst, src) \
    asm volatile("cp.async.cg.shared.global [%0], [%1], 16;" :: "r"(dst), "l"(src) : "memory")
#define CP_COMMIT() asm volatile("cp.async.commit_group;" ::: "memory")
#define CP_WAIT1()  asm volatile("cp.async.wait_group 1;" ::: "memory")
#define CP_WAIT0()  asm volatile("cp.async.wait_group 0;" ::: "memory")

#define LDMX4(r0, r1, r2, r3, a) \
    asm volatile("ldmatrix.sync.aligned.m8n8.x4.shared.b16 {%0,%1,%2,%3}, [%4];" \
        : "=r"(r0), "=r"(r1), "=r"(r2), "=r"(r3) : "r"(a))

#define MMA_BF16(d, a, b0, b1) \
    asm volatile("mma.sync.aligned.m16n8k16.row.col.f32.bf16.bf16.f32 " \
        "{%0,%1,%2,%3}, {%4,%5,%6,%7}, {%8,%9}, {%0,%1,%2,%3};" \
        : "+f"((d)[0]), "+f"((d)[1]), "+f"((d)[2]), "+f"((d)[3]) \
        : "r"((a)[0]), "r"((a)[1]), "r"((a)[2]), "r"((a)[3]), "r"(b0), "r"(b1))

// ================= scratch =================
__device__ float g_xe [NROWS * CDIM];
__device__ float g_xn [NROWS * CDIM];
__device__ float g_h  [NROWS * CDIM];
__device__ float g_att[NROWS * CDIM];
__device__ float g_s1 [NROWS];
__device__ float g_s2 [NROWS];
__device__ float g_sorted[NROWS];
__device__ int   g_perm  [NROWS];
__device__ float g_wpos  [NROWS];
__device__ float g_wneg  [NROWS];
__device__ float g_Apre[(NROWS + 1) * CDIM];
__device__ float g_Asuf[(NROWS + 1) * CDIM];
__device__ float g_Zpre[NROWS + 1];
__device__ float g_Zsuf[NROWS + 1];
__device__ float g_cpos[NCHUNK * CDIM];
__device__ float g_cneg[NCHUNK * CDIM];
__device__ float g_offp[NCHUNK * CDIM];
__device__ float g_offn[NCHUNK * CDIM];
__device__ float g_zcp[NCHUNK], g_zcn[NCHUNK];
__device__ float g_zoffp[NCHUNK], g_zoffn[NCHUNK];
// bf16 hi/lo split buffers
__device__ __nv_bfloat16 g_enc_h [NROWS * EDIM], g_enc_l [NROWS * EDIM];
__device__ __nv_bfloat16 g_wenc_h[CDIM * EDIM],  g_wenc_l[CDIM * EDIM];
__device__ __nv_bfloat16 g_xn_h  [NROWS * CDIM], g_xn_l  [NROWS * CDIM];
__device__ __nv_bfloat16 g_att_h [NROWS * CDIM], g_att_l [NROWS * CDIM];
__device__ __nv_bfloat16 g_w0_h  [2 * CDIM * CDIM], g_w0_l[2 * CDIM * CDIM];
__device__ __nv_bfloat16 g_w1_h  [2 * CDIM * CDIM], g_w1_l[2 * CDIM * CDIM];

// ================= fp32 -> bf16 hi/lo split =================
__global__ __launch_bounds__(256)
void convert_kernel(const float* __restrict__ in,
                    __nv_bfloat16* __restrict__ hi,
                    __nv_bfloat16* __restrict__ lo, int n4)
{
    int i = blockIdx.x * 256 + threadIdx.x;
    if (i >= n4) return;
    float4 v = ((const float4*)in)[i];
    __nv_bfloat16 h0 = __float2bfloat16_rn(v.x);
    __nv_bfloat16 h1 = __float2bfloat16_rn(v.y);
    __nv_bfloat16 h2 = __float2bfloat16_rn(v.z);
    __nv_bfloat16 h3 = __float2bfloat16_rn(v.w);
    __nv_bfloat162 H0; H0.x = h0; H0.y = h1;
    __nv_bfloat162 H1; H1.x = h2; H1.y = h3;
    __nv_bfloat162 L0, L1;
    L0.x = __float2bfloat16_rn(v.x - __bfloat162float(h0));
    L0.y = __float2bfloat16_rn(v.y - __bfloat162float(h1));
    L1.x = __float2bfloat16_rn(v.z - __bfloat162float(h2));
    L1.y = __float2bfloat16_rn(v.w - __bfloat162float(h3));
    ((__nv_bfloat162*)hi)[i * 2 + 0] = H0;
    ((__nv_bfloat162*)hi)[i * 2 + 1] = H1;
    ((__nv_bfloat162*)lo)[i * 2 + 0] = L0;
    ((__nv_bfloat162*)lo)[i * 2 + 1] = L1;
}

// ================= mma.sync split-bf16 GEMM =================
// C[M,N] = A[M,K] @ B[N,K]^T. CTA tile 128x128, K-panel 32, double buffered.
// modes: 0: C=acc   1: C=acc+addmat+bias[n]   2: C=elu(acc)*scale   3: C+=elu(acc)*scale
#define PADB   80                    // padded row stride in bytes (40 bf16)
#define MAT_B  (128 * PADB)          // 10240 bytes per matrix per split
#define STAGE_B (4 * MAT_B)          // Ah, Al, Bh, Bl
#define SMEM_GEMM_TOTAL (2 * STAGE_B)  // 81920

__global__ __launch_bounds__(256, 1)
void gemm_mma(const __nv_bfloat16* __restrict__ Ahi, const __nv_bfloat16* __restrict__ Alo,
              const __nv_bfloat16* __restrict__ Bhi, const __nv_bfloat16* __restrict__ Blo,
              float* __restrict__ Cmat, int M, int N, int K, int mode,
              const float* __restrict__ addmat, const float* __restrict__ bias, float scale)
{
    extern __shared__ char smem[];
    const uint32_t sb = smem_u32(smem);
    const int tid = threadIdx.x;
    const int lane = tid & 31;
    const int wid = tid >> 5;
    const int warp_m = wid & 1;     // 2 warps in M
    const int warp_n = wid >> 1;    // 4 warps in N
    const int bx = blockIdx.x;      // N tile
    const int by = blockIdx.y;      // M tile

    // loader indices: 2 chunks per thread per matrix
    const int idx0 = tid, idx1 = tid + 256;
    const int r0 = idx0 >> 2, c0 = idx0 & 3;
    const int r1 = idx1 >> 2, c1 = idx1 & 3;

    const size_t a_g0 = (size_t)(by * 128 + r0) * K + c0 * 8;
    const size_t a_g1 = (size_t)(by * 128 + r1) * K + c1 * 8;
    const size_t b_g0 = (size_t)(bx * 128 + r0) * K + c0 * 8;
    const size_t b_g1 = (size_t)(bx * 128 + r1) * K + c1 * 8;
    const uint32_t s_o0 = r0 * PADB + c0 * 16;
    const uint32_t s_o1 = r1 * PADB + c1 * 16;

    const int NP = K >> 5;

    // ---- issue stage 0 ----
    {
        const uint32_t st = sb;
        CP_ASYNC(st + s_o0,             Ahi + a_g0);
        CP_ASYNC(st + s_o1,             Ahi + a_g1);
        CP_ASYNC(st + MAT_B + s_o0,     Alo + a_g0);
        CP_ASYNC(st + MAT_B + s_o1,     Alo + a_g1);
        CP_ASYNC(st + 2 * MAT_B + s_o0, Bhi + b_g0);
        CP_ASYNC(st + 2 * MAT_B + s_o1, Bhi + b_g1);
        CP_ASYNC(st + 3 * MAT_B + s_o0, Blo + b_g0);
        CP_ASYNC(st + 3 * MAT_B + s_o1, Blo + b_g1);
        CP_COMMIT();
    }

    float acc[4][4][4];
#pragma unroll
    for (int i = 0; i < 4; i++)
#pragma unroll
        for (int j = 0; j < 4; j++)
#pragma unroll
            for (int q = 0; q < 4; q++) acc[i][j][q] = 0.f;

    // ldmatrix per-lane address components
    const int lr = lane & 7, lsub = lane >> 3;
    const int a_moff = (lsub & 1) * 8 + lr;          // row within 16
    const int a_ksub = lsub >> 1;                    // chunk +0/+1
    const int b_noff = (lsub >> 1) * 8 + lr;
    const int b_ksub = lsub & 1;

    for (int i = 0; i < NP; i++) {
        const uint32_t st = sb + (uint32_t)(i & 1) * STAGE_B;
        if (i + 1 < NP) {
            const uint32_t st2 = sb + (uint32_t)((i + 1) & 1) * STAGE_B;
            const size_t ko = (size_t)(i + 1) * 32;
            CP_ASYNC(st2 + s_o0,             Ahi + a_g0 + ko);
            CP_ASYNC(st2 + s_o1,             Ahi + a_g1 + ko);
            CP_ASYNC(st2 + MAT_B + s_o0,     Alo + a_g0 + ko);
            CP_ASYNC(st2 + MAT_B + s_o1,     Alo + a_g1 + ko);
            CP_ASYNC(st2 + 2 * MAT_B + s_o0, Bhi + b_g0 + ko);
            CP_ASYNC(st2 + 2 * MAT_B + s_o1, Bhi + b_g1 + ko);
            CP_ASYNC(st2 + 3 * MAT_B + s_o0, Blo + b_g0 + ko);
            CP_ASYNC(st2 + 3 * MAT_B + s_o1, Blo + b_g1 + ko);
            CP_COMMIT();
            CP_WAIT1();
        } else {
            CP_WAIT0();
        }
        __syncthreads();

#pragma unroll
        for (int ks = 0; ks < 2; ks++) {           // two k16 steps per panel
            const int kc = ks * 2;                 // base 8-chunk index
            uint32_t ah[4][4], al[4][4];
            const uint32_t a_row_base = st;
#pragma unroll
            for (int mi = 0; mi < 4; mi++) {
                uint32_t addr = a_row_base
                    + (uint32_t)(warp_m * 64 + mi * 16 + a_moff) * PADB
                    + (uint32_t)(kc + a_ksub) * 16;
                LDMX4(ah[mi][0], ah[mi][1], ah[mi][2], ah[mi][3], addr);
                LDMX4(al[mi][0], al[mi][1], al[mi][2], al[mi][3], addr + MAT_B);
            }
            uint32_t bh[2][4], bl[2][4];
#pragma unroll
            for (int p = 0; p < 2; p++) {
                uint32_t addr = st + 2 * MAT_B
                    + (uint32_t)(warp_n * 32 + p * 16 + b_noff) * PADB
                    + (uint32_t)(kc + b_ksub) * 16;
                LDMX4(bh[p][0], bh[p][1], bh[p][2], bh[p][3], addr);
                LDMX4(bl[p][0], bl[p][1], bl[p][2], bl[p][3], addr + MAT_B);
            }
#pragma unroll
            for (int mi = 0; mi < 4; mi++) {
#pragma unroll
                for (int p = 0; p < 2; p++) {
#pragma unroll
                    for (int q = 0; q < 2; q++) {
                        const int ni = p * 2 + q;
                        MMA_BF16(acc[mi][ni], ah[mi], bh[p][q * 2], bh[p][q * 2 + 1]);
                        MMA_BF16(acc[mi][ni], ah[mi], bl[p][q * 2], bl[p][q * 2 + 1]);
                        MMA_BF16(acc[mi][ni], al[mi], bh[p][q * 2], bh[p][q * 2 + 1]);
                    }
                }
            }
        }
        __syncthreads();
    }

    // ---- epilogue ----
    const int mbase = by * 128 + warp_m * 64 + (lane >> 2);
    const int nbase = bx * 128 + warp_n * 32 + (lane & 3) * 2;
#pragma unroll
    for (int mi = 0; mi < 4; mi++) {
#pragma unroll
        for (int ni = 0; ni < 4; ni++) {
            const int n = nbase + ni * 8;
#pragma unroll
            for (int half = 0; half < 2; half++) {
                const int m = mbase + mi * 16 + half * 8;
                float vx = acc[mi][ni][half * 2 + 0];
                float vy = acc[mi][ni][half * 2 + 1];
                const size_t idx = (size_t)m * N + n;
                if (mode == 1) {
                    float2 a = *(const float2*)(addmat + idx);
                    vx += a.x + bias[n];
                    vy += a.y + bias[n + 1];
                } else if (mode >= 2) {
                    vx = ((vx > 0.f) ? vx : expm1f(vx)) * scale;
                    vy = ((vy > 0.f) ? vy : expm1f(vy)) * scale;
                    if (mode == 3) {
                        float2 c = *(const float2*)(Cmat + idx);
                        vx += c.x; vy += c.y;
                    }
                }
                float2 o; o.x = vx; o.y = vy;
                *(float2*)(Cmat + idx) = o;
            }
        }
    }
}

// ================= row LayerNorm =================
__global__ __launch_bounds__(128)
void ln_kernel(const float* __restrict__ in, float* __restrict__ out,
               const float* __restrict__ g, const float* __restrict__ b)
{
    const int row = blockIdx.x;
    const float* x = in + (size_t)row * CDIM;
    float v[4];
    float s = 0.f, ss = 0.f;
#pragma unroll
    for (int t = 0; t < 4; t++) {
        v[t] = x[threadIdx.x + 128 * t];
        s += v[t]; ss += v[t] * v[t];
    }
    __shared__ float rs[4], rss[4];
#pragma unroll
    for (int o = 16; o; o >>= 1) {
        s  += __shfl_down_sync(0xffffffffu, s,  o);
        ss += __shfl_down_sync(0xffffffffu, ss, o);
    }
    if ((threadIdx.x & 31) == 0) { rs[threadIdx.x >> 5] = s; rss[threadIdx.x >> 5] = ss; }
    __syncthreads();
    float S  = rs[0] + rs[1] + rs[2] + rs[3];
    float SS = rss[0] + rss[1] + rss[2] + rss[3];
    float mu  = S * (1.f / CDIM);
    float var = SS * (1.f / CDIM) - mu * mu;
    float inv = rsqrtf(var + 1e-5f);
#pragma unroll
    for (int t = 0; t < 4; t++) {
        int c = threadIdx.x + 128 * t;
        out[(size_t)row * CDIM + c] = (v[t] - mu) * inv * g[c] + b[c];
    }
}

// ================= s1/s2 =================
__global__ void s_kernel(const float* __restrict__ h, const float* __restrict__ wa)
{
    const int row = blockIdx.x * 8 + threadIdx.y;
    const int lane = threadIdx.x;
    const float* hr = h + (size_t)row * CDIM;
    float a = 0.f, bv = 0.f;
#pragma unroll
    for (int t = 0; t < 16; t++) {
        int c = lane + 32 * t;
        float hv = hr[c];
        a  = fmaf(hv, wa[c], a);
        bv = fmaf(hv, wa[CDIM + c], bv);
    }
#pragma unroll
    for (int o = 16; o; o >>= 1) {
        a  += __shfl_down_sync(0xffffffffu, a,  o);
        bv += __shfl_down_sync(0xffffffffu, bv, o);
    }
    if (lane == 0) { g_s1[row] = a; g_s2[row] = bv; }
}

// ================= rank (sort by counting) =================
__global__ __launch_bounds__(256)
void rank_kernel()
{
    __shared__ float4 sh[NROWS / 4];
    for (int t = threadIdx.x; t < NROWS / 4; t += 256)
        sh[t] = ((const float4*)g_s2)[t];
    __syncthreads();
    const int i = blockIdx.x * 256 + threadIdx.x;
    const float v = g_s2[i];
    int r = 0;
#pragma unroll 4
    for (int jj = 0; jj < NROWS / 4; jj++) {
        float4 u = sh[jj];
        int j = jj * 4;
        r += (u.x < v) || (u.x == v && j + 0 < i);
        r += (u.y < v) || (u.y == v && j + 1 < i);
        r += (u.z < v) || (u.z == v && j + 2 < i);
        r += (u.w < v) || (u.w == v && j + 3 < i);
    }
    g_sorted[r] = v;
    g_perm[r]   = i;
    g_wpos[r]   = expf(v);
    g_wneg[r]   = expf(0.01f * v);
}

// ================= chunked scan: phase 1 =================
__global__ __launch_bounds__(128)
void chunk_sum_kernel()
{
    const int s = blockIdx.x, c = blockIdx.y;
    const int col = s * 128 + threadIdx.x;
    const int u0 = c * CHUNK;
    float accp = 0.f, accn = 0.f;
    float zp = 0.f, zn = 0.f;
    const bool do_z = (s == 0 && threadIdx.x == 0);
#pragma unroll 4
    for (int t = 0; t < CHUNK; t++) {
        const int u = u0 + t;
        const int r = g_perm[u];
        const float wp = g_wpos[u], wn = g_wneg[u];
        const float hv = g_h[(size_t)r * CDIM + col];
        accp = fmaf(wp, hv, accp);
        accn = fmaf(wn, hv, accn);
        if (do_z) { zp += wp; zn += wn; }
    }
    g_cpos[c * CDIM + col] = accp;
    g_cneg[c * CDIM + col] = accn;
    if (do_z) { g_zcp[c] = zp; g_zcn[c] = zn; }
}

// ================= chunked scan: phase 2 =================
__global__ __launch_bounds__(512)
void chunk_scan_kernel()
{
    const int col = threadIdx.x;
    float run = 0.f;
    for (int c = 0; c < NCHUNK; c++) {
        g_offn[c * CDIM + col] = run;
        run += g_cneg[c * CDIM + col];
    }
    run = 0.f;
    for (int c = NCHUNK - 1; c >= 0; c--) {
        g_offp[c * CDIM + col] = run;
        run += g_cpos[c * CDIM + col];
    }
    if (col == 0) {
        float zr = 0.f;
        for (int c = 0; c < NCHUNK; c++) { g_zoffn[c] = zr; zr += g_zcn[c]; }
    } else if (col == 1) {
        float zr = 0.f;
        for (int c = NCHUNK - 1; c >= 0; c--) { g_zoffp[c] = zr; zr += g_zcp[c]; }
    }
}

// ================= chunked scan: phase 3 =================
__global__ __launch_bounds__(128)
void scan_write_kernel()
{
    const int s = blockIdx.x, c = blockIdx.y;
    const int col = s * 128 + threadIdx.x;
    const int u0 = c * CHUNK;

    float accn    = g_offn[c * CDIM + col];
    const float base_suf = g_offp[c * CDIM + col] + g_cpos[c * CDIM + col];
    float pp = 0.f;

    const bool do_z = (s == 0 && threadIdx.x == 0);
    float zn = 0.f, zbs = 0.f, zpp = 0.f;
    if (do_z) { zn = g_zoffn[c]; zbs = g_zoffp[c] + g_zcp[c]; }

    if (c == 0) {
        g_Apre[col] = 0.f;
        if (do_z) g_Zpre[0] = 0.f;
    }
    if (c == NCHUNK - 1) {
        g_Asuf[(size_t)NROWS * CDIM + col] = 0.f;
        if (do_z) g_Zsuf[NROWS] = 0.f;
    }

#pragma unroll 4
    for (int t = 0; t < CHUNK; t++) {
        const int u = u0 + t;
        const int r = g_perm[u];
        const float wp = g_wpos[u], wn = g_wneg[u];
        const float hv = g_h[(size_t)r * CDIM + col];
        g_Asuf[(size_t)u * CDIM + col] = base_suf - pp;
        pp   = fmaf(wp, hv, pp);
        accn = fmaf(wn, hv, accn);
        g_Apre[(size_t)(u + 1) * CDIM + col] = accn;
        if (do_z) {
            g_Zsuf[u] = zbs - zpp;
            zpp += wp;
            zn  += wn;
            g_Zpre[u + 1] = zn;
        }
    }
}

// ================= combine + residual + LN2 =================
__global__ __launch_bounds__(128)
void combine_kernel(const float* __restrict__ ln2g, const float* __restrict__ ln2b)
{
    const int row = blockIdx.x;
    __shared__ int sk;
    __shared__ float rs[4], rss[4];
    if (threadIdx.x == 0) {
        float thr = -g_s1[row];
        int lo = 0, hi = NROWS;
        while (lo < hi) {
            int mid = (lo + hi) >> 1;
            if (g_sorted[mid] <= thr) lo = mid + 1; else hi = mid;
        }
        sk = lo;
    }
    __syncthreads();
    const int k = sk;
    const float s1v = g_s1[row];
    const float ap = expf(s1v);
    const float an = expf(0.01f * s1v);
    const float den = ap * g_Zsuf[k] + an * g_Zpre[k];
    const float inv_den = 1.f / den;

    float v[4]; float s = 0.f, ss = 0.f;
#pragma unroll
    for (int t = 0; t < 4; t++) {
        int c = threadIdx.x + 128 * t;
        float num = ap * g_Asuf[(size_t)k * CDIM + c] + an * g_Apre[(size_t)k * CDIM + c];
        float val = num * inv_den + g_xe[(size_t)row * CDIM + c];
        v[t] = val; s += val; ss += val * val;
    }
#pragma unroll
    for (int o = 16; o; o >>= 1) {
        s  += __shfl_down_sync(0xffffffffu, s,  o);
        ss += __shfl_down_sync(0xffffffffu, ss, o);
    }
    if ((threadIdx.x & 31) == 0) { rs[threadIdx.x >> 5] = s; rss[threadIdx.x >> 5] = ss; }
    __syncthreads();
    float S  = rs[0] + rs[1] + rs[2] + rs[3];
    float SS = rss[0] + rss[1] + rss[2] + rss[3];
    float mu  = S * (1.f / CDIM);
    float var = SS * (1.f / CDIM) - mu * mu;
    float inv = rsqrtf(var + 1e-5f);
#pragma unroll
    for (int t = 0; t < 4; t++) {
        int c = threadIdx.x + 128 * t;
        g_att[(size_t)row * CDIM + c] = (v[t] - mu) * inv * ln2g[c] + ln2b[c];
    }
}

// ================= launch =================
extern "C" void kernel_launch(void* const* d_in, const int* in_sizes, int n_in,
                              void* d_out, int out_size)
{
    const float* x     = (const float*)d_in[0];
    const float* enc   = (const float*)d_in[1];
    const float* W_enc = (const float*)d_in[2];
    const float* b_enc = (const float*)d_in[3];
    const float* ln1g  = (const float*)d_in[4];
    const float* ln1b  = (const float*)d_in[5];
    const float* ln2g  = (const float*)d_in[6];
    const float* ln2b  = (const float*)d_in[7];
    const float* W0    = (const float*)d_in[8];
    const float* W1    = (const float*)d_in[9];
    const float* Wa    = (const float*)d_in[10];
    float* out = (float*)d_out;

    static int attr_done = 0;
    if (!attr_done) {
        cudaFuncSetAttribute(gemm_mma, cudaFuncAttributeMaxDynamicSharedMemorySize, SMEM_GEMM_TOTAL);
        attr_done = 1;
    }

    void *p_xe, *p_xn, *p_h, *p_att;
    cudaGetSymbolAddress(&p_xe,  g_xe);
    cudaGetSymbolAddress(&p_xn,  g_xn);
    cudaGetSymbolAddress(&p_h,   g_h);
    cudaGetSymbolAddress(&p_att, g_att);
    float* xe  = (float*)p_xe;
    float* xn  = (float*)p_xn;
    float* h   = (float*)p_h;
    float* att = (float*)p_att;

    void *p_ench, *p_encl, *p_wench, *p_wencl, *p_xnh, *p_xnl, *p_atth, *p_attl;
    void *p_w0h, *p_w0l, *p_w1h, *p_w1l;
    cudaGetSymbolAddress(&p_ench,  g_enc_h);  cudaGetSymbolAddress(&p_encl,  g_enc_l);
    cudaGetSymbolAddress(&p_wench, g_wenc_h); cudaGetSymbolAddress(&p_wencl, g_wenc_l);
    cudaGetSymbolAddress(&p_xnh,   g_xn_h);   cudaGetSymbolAddress(&p_xnl,   g_xn_l);
    cudaGetSymbolAddress(&p_atth,  g_att_h);  cudaGetSymbolAddress(&p_attl,  g_att_l);
    cudaGetSymbolAddress(&p_w0h,   g_w0_h);   cudaGetSymbolAddress(&p_w0l,   g_w0_l);
    cudaGetSymbolAddress(&p_w1h,   g_w1_h);   cudaGetSymbolAddress(&p_w1l,   g_w1_l);
    __nv_bfloat16* ench  = (__nv_bfloat16*)p_ench;  __nv_bfloat16* encl  = (__nv_bfloat16*)p_encl;
    __nv_bfloat16* wench = (__nv_bfloat16*)p_wench; __nv_bfloat16* wencl = (__nv_bfloat16*)p_wencl;
    __nv_bfloat16* xnh   = (__nv_bfloat16*)p_xnh;   __nv_bfloat16* xnl   = (__nv_bfloat16*)p_xnl;
    __nv_bfloat16* atth  = (__nv_bfloat16*)p_atth;  __nv_bfloat16* attl  = (__nv_bfloat16*)p_attl;
    __nv_bfloat16* w0h   = (__nv_bfloat16*)p_w0h;   __nv_bfloat16* w0l   = (__nv_bfloat16*)p_w0l;
    __nv_bfloat16* w1h   = (__nv_bfloat16*)p_w1h;   __nv_bfloat16* w1l   = (__nv_bfloat16*)p_w1l;

    dim3 ggrid(CDIM / 128, NROWS / 128);   // (4, 64)
    dim3 scan_grid(CDIM / 128, NCHUNK);

    // conversions of inputs
    convert_kernel<<<(NROWS * EDIM / 4 + 255) / 256, 256>>>(enc, ench, encl, NROWS * EDIM / 4);
    convert_kernel<<<(CDIM * EDIM / 4 + 255) / 256, 256>>>(W_enc, wench, wencl, CDIM * EDIM / 4);
    convert_kernel<<<(2 * CDIM * CDIM / 4 + 255) / 256, 256>>>(W0, w0h, w0l, 2 * CDIM * CDIM / 4);
    convert_kernel<<<(2 * CDIM * CDIM / 4 + 255) / 256, 256>>>(W1, w1h, w1l, 2 * CDIM * CDIM / 4);

    // 1) xe = x + enc @ W_enc^T + b_enc
    gemm_mma<<<ggrid, 256, SMEM_GEMM_TOTAL>>>(ench, encl, wench, wencl, xe,
                                              NROWS, CDIM, EDIM, 1, x, b_enc, 1.f);
    // 2) xn = LN1(xe); convert
    ln_kernel<<<NROWS, 128>>>(xe, xn, ln1g, ln1b);
    convert_kernel<<<(NROWS * CDIM / 4 + 255) / 256, 256>>>(xn, xnh, xnl, NROWS * CDIM / 4);

    for (int head = 0; head < 2; head++) {
        const __nv_bfloat16* W0hh = w0h + (size_t)head * CDIM * CDIM;
        const __nv_bfloat16* W0hl = w0l + (size_t)head * CDIM * CDIM;
        const __nv_bfloat16* W1hh = w1h + (size_t)head * CDIM * CDIM;
        const __nv_bfloat16* W1hl = w1l + (size_t)head * CDIM * CDIM;
        const float* Wah = Wa + (size_t)head * 2 * CDIM;

        // 3) h = xn @ W0h^T
        gemm_mma<<<ggrid, 256, SMEM_GEMM_TOTAL>>>(xnh, xnl, W0hh, W0hl, h,
                                                  NROWS, CDIM, CDIM, 0, nullptr, nullptr, 1.f);
        // 4) s1, s2
        s_kernel<<<NROWS / 8, dim3(32, 8)>>>(h, Wah);
        // 5) rank + exp weights
        rank_kernel<<<NROWS / 256, 256>>>();
        // 6) chunked scans
        chunk_sum_kernel<<<scan_grid, 128>>>();
        chunk_scan_kernel<<<1, 512>>>();
        scan_write_kernel<<<scan_grid, 128>>>();
        // 7) combine + residual + LN2
        combine_kernel<<<NROWS, 128>>>(ln2g, ln2b);
        // 8) out (+)= elu(att @ W1h^T) / 2
        convert_kernel<<<(NROWS * CDIM / 4 + 255) / 256, 256>>>(att, atth, attl, NROWS * CDIM / 4);
        gemm_mma<<<ggrid, 256, SMEM_GEMM_TOTAL>>>(atth, attl, W1hh, W1hl, out,
                                                  NROWS, CDIM, CDIM, head == 0 ? 2 : 3,
                                                  nullptr, nullptr, 0.5f);
    }
}

// round 5
// speedup vs baseline: 7.1138x; 1.1040x over previous
#include <cuda_runtime.h>
#include <cuda_bf16.h>
#include <math.h>
#include <stdint.h>

#define NROWS 8192
#define CDIM  512
#define EDIM  256
#define CHUNK 128
#define NCHUNK (NROWS / CHUNK)   // 64

// ================= helpers =================
__device__ __forceinline__ uint32_t smem_u32(const void* p) {
    uint32_t a;
    asm("{ .reg .u64 t; cvta.to.shared.u64 t, %1; cvt.u32.u64 %0, t; }" : "=r"(a) : "l"(p));
    return a;
}
#define CP_ASYNC(dst, src) \
    asm volatile("cp.async.cg.shared.global [%0], [%1], 16;" :: "r"(dst), "l"(src) : "memory")
#define CP_COMMIT() asm volatile("cp.async.commit_group;" ::: "memory")
#define CP_WAIT1()  asm volatile("cp.async.wait_group 1;" ::: "memory")
#define CP_WAIT0()  asm volatile("cp.async.wait_group 0;" ::: "memory")

#define LDMX4(r0, r1, r2, r3, a) \
    asm volatile("ldmatrix.sync.aligned.m8n8.x4.shared.b16 {%0,%1,%2,%3}, [%4];" \
        : "=r"(r0), "=r"(r1), "=r"(r2), "=r"(r3) : "r"(a))

#define MMA_BF16(d, a, b0, b1) \
    asm volatile("mma.sync.aligned.m16n8k16.row.col.f32.bf16.bf16.f32 " \
        "{%0,%1,%2,%3}, {%4,%5,%6,%7}, {%8,%9}, {%0,%1,%2,%3};" \
        : "+f"((d)[0]), "+f"((d)[1]), "+f"((d)[2]), "+f"((d)[3]) \
        : "r"((a)[0]), "r"((a)[1]), "r"((a)[2]), "r"((a)[3]), "r"(b0), "r"(b1))

// pack 4 floats -> 4 bf16 hi + 4 bf16 lo (two bf162 each)
__device__ __forceinline__ void split4(float x, float y, float z, float w,
                                       uint2& hi, uint2& lo)
{
    __nv_bfloat16 h0 = __float2bfloat16_rn(x);
    __nv_bfloat16 h1 = __float2bfloat16_rn(y);
    __nv_bfloat16 h2 = __float2bfloat16_rn(z);
    __nv_bfloat16 h3 = __float2bfloat16_rn(w);
    __nv_bfloat162 H0; H0.x = h0; H0.y = h1;
    __nv_bfloat162 H1; H1.x = h2; H1.y = h3;
    __nv_bfloat162 L0, L1;
    L0.x = __float2bfloat16_rn(x - __bfloat162float(h0));
    L0.y = __float2bfloat16_rn(y - __bfloat162float(h1));
    L1.x = __float2bfloat16_rn(z - __bfloat162float(h2));
    L1.y = __float2bfloat16_rn(w - __bfloat162float(h3));
    hi.x = *(uint32_t*)&H0; hi.y = *(uint32_t*)&H1;
    lo.x = *(uint32_t*)&L0; lo.y = *(uint32_t*)&L1;
}

// ================= scratch =================
__device__ float g_xe [NROWS * CDIM];
__device__ float g_h  [NROWS * CDIM];
__device__ float g_s1 [NROWS];
__device__ float g_s2 [NROWS];
__device__ float g_sorted[NROWS];
__device__ int   g_perm  [NROWS];
__device__ float g_wpos  [NROWS];
__device__ float g_wneg  [NROWS];
__device__ float g_Apre[(NROWS + 1) * CDIM];
__device__ float g_Asuf[(NROWS + 1) * CDIM];
__device__ float g_Zpre[NROWS + 1];
__device__ float g_Zsuf[NROWS + 1];
__device__ float g_cpos[NCHUNK * CDIM];
__device__ float g_cneg[NCHUNK * CDIM];
__device__ float g_offp[NCHUNK * CDIM];
__device__ float g_offn[NCHUNK * CDIM];
__device__ float g_zcp[NCHUNK], g_zcn[NCHUNK];
__device__ float g_zoffp[NCHUNK], g_zoffn[NCHUNK];
// bf16 hi/lo split buffers
__device__ __nv_bfloat16 g_enc_h [NROWS * EDIM], g_enc_l [NROWS * EDIM];
__device__ __nv_bfloat16 g_wenc_h[CDIM * EDIM],  g_wenc_l[CDIM * EDIM];
__device__ __nv_bfloat16 g_xn_h  [NROWS * CDIM], g_xn_l  [NROWS * CDIM];
__device__ __nv_bfloat16 g_att_h [NROWS * CDIM], g_att_l [NROWS * CDIM];
__device__ __nv_bfloat16 g_w0_h  [2 * CDIM * CDIM], g_w0_l[2 * CDIM * CDIM];
__device__ __nv_bfloat16 g_w1_h  [2 * CDIM * CDIM], g_w1_l[2 * CDIM * CDIM];

// ================= fp32 -> bf16 hi/lo split (for raw inputs) =================
__global__ __launch_bounds__(256)
void convert_kernel(const float* __restrict__ in,
                    __nv_bfloat16* __restrict__ hi,
                    __nv_bfloat16* __restrict__ lo, int n4)
{
    int i = blockIdx.x * 256 + threadIdx.x;
    if (i >= n4) return;
    float4 v = ((const float4*)in)[i];
    uint2 H, L;
    split4(v.x, v.y, v.z, v.w, H, L);
    ((uint2*)hi)[i] = H;
    ((uint2*)lo)[i] = L;
}

// ================= mma.sync split-bf16 GEMM =================
// C[M,N] = A[M,K] @ B[N,K]^T. CTA tile 128x128, K-panel 32, double buffered.
// modes: 0: C=acc   1: C=acc+addmat+bias[n]   2: C=elu(acc)*scale   3: C+=elu(acc)*scale
#define PADB   80                    // padded row stride in bytes (40 bf16)
#define MAT_B  (128 * PADB)          // 10240 bytes per matrix per split
#define STAGE_B (4 * MAT_B)          // Ah, Al, Bh, Bl
#define SMEM_GEMM_TOTAL (2 * STAGE_B)  // 81920

__global__ __launch_bounds__(256, 2)
void gemm_mma(const __nv_bfloat16* __restrict__ Ahi, const __nv_bfloat16* __restrict__ Alo,
              const __nv_bfloat16* __restrict__ Bhi, const __nv_bfloat16* __restrict__ Blo,
              float* __restrict__ Cmat, int M, int N, int K, int mode,
              const float* __restrict__ addmat, const float* __restrict__ bias, float scale)
{
    extern __shared__ char smem[];
    const uint32_t sb = smem_u32(smem);
    const int tid = threadIdx.x;
    const int lane = tid & 31;
    const int wid = tid >> 5;
    const int warp_m = wid & 1;     // 2 warps in M
    const int warp_n = wid >> 1;    // 4 warps in N
    const int bx = blockIdx.x;      // N tile
    const int by = blockIdx.y;      // M tile

    // loader indices: 2 chunks per thread per matrix
    const int idx0 = tid, idx1 = tid + 256;
    const int r0 = idx0 >> 2, c0 = idx0 & 3;
    const int r1 = idx1 >> 2, c1 = idx1 & 3;

    const size_t a_g0 = (size_t)(by * 128 + r0) * K + c0 * 8;
    const size_t a_g1 = (size_t)(by * 128 + r1) * K + c1 * 8;
    const size_t b_g0 = (size_t)(bx * 128 + r0) * K + c0 * 8;
    const size_t b_g1 = (size_t)(bx * 128 + r1) * K + c1 * 8;
    const uint32_t s_o0 = r0 * PADB + c0 * 16;
    const uint32_t s_o1 = r1 * PADB + c1 * 16;

    const int NP = K >> 5;

    // ---- issue stage 0 ----
    {
        const uint32_t st = sb;
        CP_ASYNC(st + s_o0,             Ahi + a_g0);
        CP_ASYNC(st + s_o1,             Ahi + a_g1);
        CP_ASYNC(st + MAT_B + s_o0,     Alo + a_g0);
        CP_ASYNC(st + MAT_B + s_o1,     Alo + a_g1);
        CP_ASYNC(st + 2 * MAT_B + s_o0, Bhi + b_g0);
        CP_ASYNC(st + 2 * MAT_B + s_o1, Bhi + b_g1);
        CP_ASYNC(st + 3 * MAT_B + s_o0, Blo + b_g0);
        CP_ASYNC(st + 3 * MAT_B + s_o1, Blo + b_g1);
        CP_COMMIT();
    }

    float acc[4][4][4];
#pragma unroll
    for (int i = 0; i < 4; i++)
#pragma unroll
        for (int j = 0; j < 4; j++)
#pragma unroll
            for (int q = 0; q < 4; q++) acc[i][j][q] = 0.f;

    // ldmatrix per-lane address components
    const int lr = lane & 7, lsub = lane >> 3;
    const int a_moff = (lsub & 1) * 8 + lr;          // row within 16
    const int a_ksub = lsub >> 1;                    // chunk +0/+1
    const int b_noff = (lsub >> 1) * 8 + lr;
    const int b_ksub = lsub & 1;

    for (int i = 0; i < NP; i++) {
        const uint32_t st = sb + (uint32_t)(i & 1) * STAGE_B;
        if (i + 1 < NP) {
            const uint32_t st2 = sb + (uint32_t)((i + 1) & 1) * STAGE_B;
            const size_t ko = (size_t)(i + 1) * 32;
            CP_ASYNC(st2 + s_o0,             Ahi + a_g0 + ko);
            CP_ASYNC(st2 + s_o1,             Ahi + a_g1 + ko);
            CP_ASYNC(st2 + MAT_B + s_o0,     Alo + a_g0 + ko);
            CP_ASYNC(st2 + MAT_B + s_o1,     Alo + a_g1 + ko);
            CP_ASYNC(st2 + 2 * MAT_B + s_o0, Bhi + b_g0 + ko);
            CP_ASYNC(st2 + 2 * MAT_B + s_o1, Bhi + b_g1 + ko);
            CP_ASYNC(st2 + 3 * MAT_B + s_o0, Blo + b_g0 + ko);
            CP_ASYNC(st2 + 3 * MAT_B + s_o1, Blo + b_g1 + ko);
            CP_COMMIT();
            CP_WAIT1();
        } else {
            CP_WAIT0();
        }
        __syncthreads();

#pragma unroll
        for (int ks = 0; ks < 2; ks++) {           // two k16 steps per panel
            const int kc = ks * 2;                 // base 8-chunk index
            uint32_t bh[2][4], bl[2][4];
#pragma unroll
            for (int p = 0; p < 2; p++) {
                uint32_t addr = st + 2 * MAT_B
                    + (uint32_t)(warp_n * 32 + p * 16 + b_noff) * PADB
                    + (uint32_t)(kc + b_ksub) * 16;
                LDMX4(bh[p][0], bh[p][1], bh[p][2], bh[p][3], addr);
                LDMX4(bl[p][0], bl[p][1], bl[p][2], bl[p][3], addr + MAT_B);
            }
#pragma unroll
            for (int mi = 0; mi < 4; mi++) {
                uint32_t ah[4], al[4];
                uint32_t addr = st
                    + (uint32_t)(warp_m * 64 + mi * 16 + a_moff) * PADB
                    + (uint32_t)(kc + a_ksub) * 16;
                LDMX4(ah[0], ah[1], ah[2], ah[3], addr);
                LDMX4(al[0], al[1], al[2], al[3], addr + MAT_B);
#pragma unroll
                for (int p = 0; p < 2; p++) {
#pragma unroll
                    for (int q = 0; q < 2; q++) {
                        const int ni = p * 2 + q;
                        MMA_BF16(acc[mi][ni], ah, bh[p][q * 2], bh[p][q * 2 + 1]);
                        MMA_BF16(acc[mi][ni], ah, bl[p][q * 2], bl[p][q * 2 + 1]);
                        MMA_BF16(acc[mi][ni], al, bh[p][q * 2], bh[p][q * 2 + 1]);
                    }
                }
            }
        }
        __syncthreads();
    }

    // ---- epilogue ----
    const int mbase = by * 128 + warp_m * 64 + (lane >> 2);
    const int nbase = bx * 128 + warp_n * 32 + (lane & 3) * 2;
#pragma unroll
    for (int mi = 0; mi < 4; mi++) {
#pragma unroll
        for (int ni = 0; ni < 4; ni++) {
            const int n = nbase + ni * 8;
#pragma unroll
            for (int half = 0; half < 2; half++) {
                const int m = mbase + mi * 16 + half * 8;
                float vx = acc[mi][ni][half * 2 + 0];
                float vy = acc[mi][ni][half * 2 + 1];
                const size_t idx = (size_t)m * N + n;
                if (mode == 1) {
                    float2 a = *(const float2*)(addmat + idx);
                    vx += a.x + bias[n];
                    vy += a.y + bias[n + 1];
                } else if (mode >= 2) {
                    vx = ((vx > 0.f) ? vx : expm1f(vx)) * scale;
                    vy = ((vy > 0.f) ? vy : expm1f(vy)) * scale;
                    if (mode == 3) {
                        float2 c = *(const float2*)(Cmat + idx);
                        vx += c.x; vy += c.y;
                    }
                }
                float2 o; o.x = vx; o.y = vy;
                *(float2*)(Cmat + idx) = o;
            }
        }
    }
}

// ================= row LayerNorm -> bf16 hi/lo =================
__global__ __launch_bounds__(128)
void ln_kernel(const float* __restrict__ in,
               __nv_bfloat16* __restrict__ hi, __nv_bfloat16* __restrict__ lo,
               const float* __restrict__ g, const float* __restrict__ b)
{
    const int row = blockIdx.x;
    const int tid = threadIdx.x;
    const int c = tid * 4;
    float4 v = *(const float4*)(in + (size_t)row * CDIM + c);
    float s  = v.x + v.y + v.z + v.w;
    float ss = v.x * v.x + v.y * v.y + v.z * v.z + v.w * v.w;
    __shared__ float rs[4], rss[4];
#pragma unroll
    for (int o = 16; o; o >>= 1) {
        s  += __shfl_down_sync(0xffffffffu, s,  o);
        ss += __shfl_down_sync(0xffffffffu, ss, o);
    }
    if ((tid & 31) == 0) { rs[tid >> 5] = s; rss[tid >> 5] = ss; }
    __syncthreads();
    float S  = rs[0] + rs[1] + rs[2] + rs[3];
    float SS = rss[0] + rss[1] + rss[2] + rss[3];
    float mu  = S * (1.f / CDIM);
    float var = SS * (1.f / CDIM) - mu * mu;
    float inv = rsqrtf(var + 1e-5f);
    float4 gv = *(const float4*)(g + c);
    float4 bv = *(const float4*)(b + c);
    float yx = (v.x - mu) * inv * gv.x + bv.x;
    float yy = (v.y - mu) * inv * gv.y + bv.y;
    float yz = (v.z - mu) * inv * gv.z + bv.z;
    float yw = (v.w - mu) * inv * gv.w + bv.w;
    uint2 H, L;
    split4(yx, yy, yz, yw, H, L);
    ((uint2*)(hi + (size_t)row * CDIM))[tid] = H;
    ((uint2*)(lo + (size_t)row * CDIM))[tid] = L;
}

// ================= s1/s2 =================
__global__ void s_kernel(const float* __restrict__ h, const float* __restrict__ wa)
{
    const int row = blockIdx.x * 8 + threadIdx.y;
    const int lane = threadIdx.x;
    const float* hr = h + (size_t)row * CDIM;
    float a = 0.f, bv = 0.f;
#pragma unroll
    for (int t = 0; t < 16; t++) {
        int c = lane + 32 * t;
        float hv = hr[c];
        a  = fmaf(hv, wa[c], a);
        bv = fmaf(hv, wa[CDIM + c], bv);
    }
#pragma unroll
    for (int o = 16; o; o >>= 1) {
        a  += __shfl_down_sync(0xffffffffu, a,  o);
        bv += __shfl_down_sync(0xffffffffu, bv, o);
    }
    if (lane == 0) { g_s1[row] = a; g_s2[row] = bv; }
}

// ================= rank (sort by counting) =================
__global__ __launch_bounds__(256)
void rank_kernel()
{
    __shared__ float4 sh[NROWS / 4];
    for (int t = threadIdx.x; t < NROWS / 4; t += 256)
        sh[t] = ((const float4*)g_s2)[t];
    __syncthreads();
    const int i = blockIdx.x * 256 + threadIdx.x;
    const float v = g_s2[i];
    int r = 0;
#pragma unroll 4
    for (int jj = 0; jj < NROWS / 4; jj++) {
        float4 u = sh[jj];
        int j = jj * 4;
        r += (u.x < v) || (u.x == v && j + 0 < i);
        r += (u.y < v) || (u.y == v && j + 1 < i);
        r += (u.z < v) || (u.z == v && j + 2 < i);
        r += (u.w < v) || (u.w == v && j + 3 < i);
    }
    g_sorted[r] = v;
    g_perm[r]   = i;
    g_wpos[r]   = expf(v);
    g_wneg[r]   = expf(0.01f * v);
}

// ================= chunked scan: phase 1 =================
__global__ __launch_bounds__(128)
void chunk_sum_kernel()
{
    const int s = blockIdx.x, c = blockIdx.y;
    const int col = s * 128 + threadIdx.x;
    const int u0 = c * CHUNK;
    float accp = 0.f, accn = 0.f;
    float zp = 0.f, zn = 0.f;
    const bool do_z = (s == 0 && threadIdx.x == 0);
#pragma unroll 4
    for (int t = 0; t < CHUNK; t++) {
        const int u = u0 + t;
        const int r = g_perm[u];
        const float wp = g_wpos[u], wn = g_wneg[u];
        const float hv = g_h[(size_t)r * CDIM + col];
        accp = fmaf(wp, hv, accp);
        accn = fmaf(wn, hv, accn);
        if (do_z) { zp += wp; zn += wn; }
    }
    g_cpos[c * CDIM + col] = accp;
    g_cneg[c * CDIM + col] = accn;
    if (do_z) { g_zcp[c] = zp; g_zcn[c] = zn; }
}

// ================= chunked scan: phase 2 =================
__global__ __launch_bounds__(512)
void chunk_scan_kernel()
{
    const int col = threadIdx.x;
    float run = 0.f;
    for (int c = 0; c < NCHUNK; c++) {
        g_offn[c * CDIM + col] = run;
        run += g_cneg[c * CDIM + col];
    }
    run = 0.f;
    for (int c = NCHUNK - 1; c >= 0; c--) {
        g_offp[c * CDIM + col] = run;
        run += g_cpos[c * CDIM + col];
    }
    if (col == 0) {
        float zr = 0.f;
        for (int c = 0; c < NCHUNK; c++) { g_zoffn[c] = zr; zr += g_zcn[c]; }
    } else if (col == 1) {
        float zr = 0.f;
        for (int c = NCHUNK - 1; c >= 0; c--) { g_zoffp[c] = zr; zr += g_zcp[c]; }
    }
}

// ================= chunked scan: phase 3 =================
__global__ __launch_bounds__(128)
void scan_write_kernel()
{
    const int s = blockIdx.x, c = blockIdx.y;
    const int col = s * 128 + threadIdx.x;
    const int u0 = c * CHUNK;

    float accn    = g_offn[c * CDIM + col];
    const float base_suf = g_offp[c * CDIM + col] + g_cpos[c * CDIM + col];
    float pp = 0.f;

    const bool do_z = (s == 0 && threadIdx.x == 0);
    float zn = 0.f, zbs = 0.f, zpp = 0.f;
    if (do_z) { zn = g_zoffn[c]; zbs = g_zoffp[c] + g_zcp[c]; }

    if (c == 0) {
        g_Apre[col] = 0.f;
        if (do_z) g_Zpre[0] = 0.f;
    }
    if (c == NCHUNK - 1) {
        g_Asuf[(size_t)NROWS * CDIM + col] = 0.f;
        if (do_z) g_Zsuf[NROWS] = 0.f;
    }

#pragma unroll 4
    for (int t = 0; t < CHUNK; t++) {
        const int u = u0 + t;
        const int r = g_perm[u];
        const float wp = g_wpos[u], wn = g_wneg[u];
        const float hv = g_h[(size_t)r * CDIM + col];
        g_Asuf[(size_t)u * CDIM + col] = base_suf - pp;
        pp   = fmaf(wp, hv, pp);
        accn = fmaf(wn, hv, accn);
        g_Apre[(size_t)(u + 1) * CDIM + col] = accn;
        if (do_z) {
            g_Zsuf[u] = zbs - zpp;
            zpp += wp;
            zn  += wn;
            g_Zpre[u + 1] = zn;
        }
    }
}

// ================= combine + residual + LN2 -> bf16 hi/lo =================
__global__ __launch_bounds__(128)
void combine_kernel(const float* __restrict__ ln2g, const float* __restrict__ ln2b)
{
    const int row = blockIdx.x;
    const int tid = threadIdx.x;
    __shared__ int sk;
    __shared__ float rs[4], rss[4];
    if (tid == 0) {
        float thr = -g_s1[row];
        int lo = 0, hi = NROWS;
        while (lo < hi) {
            int mid = (lo + hi) >> 1;
            if (g_sorted[mid] <= thr) lo = mid + 1; else hi = mid;
        }
        sk = lo;
    }
    __syncthreads();
    const int k = sk;
    const float s1v = g_s1[row];
    const float ap = expf(s1v);
    const float an = expf(0.01f * s1v);
    const float den = ap * g_Zsuf[k] + an * g_Zpre[k];
    const float inv_den = 1.f / den;

    const int c = tid * 4;
    float4 suf = *(const float4*)(g_Asuf + (size_t)k * CDIM + c);
    float4 pre = *(const float4*)(g_Apre + (size_t)k * CDIM + c);
    float4 xev = *(const float4*)(g_xe + (size_t)row * CDIM + c);
    float vx = (ap * suf.x + an * pre.x) * inv_den + xev.x;
    float vy = (ap * suf.y + an * pre.y) * inv_den + xev.y;
    float vz = (ap * suf.z + an * pre.z) * inv_den + xev.z;
    float vw = (ap * suf.w + an * pre.w) * inv_den + xev.w;

    float s  = vx + vy + vz + vw;
    float ss = vx * vx + vy * vy + vz * vz + vw * vw;
#pragma unroll
    for (int o = 16; o; o >>= 1) {
        s  += __shfl_down_sync(0xffffffffu, s,  o);
        ss += __shfl_down_sync(0xffffffffu, ss, o);
    }
    if ((tid & 31) == 0) { rs[tid >> 5] = s; rss[tid >> 5] = ss; }
    __syncthreads();
    float S  = rs[0] + rs[1] + rs[2] + rs[3];
    float SS = rss[0] + rss[1] + rss[2] + rss[3];
    float mu  = S * (1.f / CDIM);
    float var = SS * (1.f / CDIM) - mu * mu;
    float inv = rsqrtf(var + 1e-5f);
    float4 gv = *(const float4*)(ln2g + c);
    float4 bv = *(const float4*)(ln2b + c);
    float yx = (vx - mu) * inv * gv.x + bv.x;
    float yy = (vy - mu) * inv * gv.y + bv.y;
    float yz = (vz - mu) * inv * gv.z + bv.z;
    float yw = (vw - mu) * inv * gv.w + bv.w;
    uint2 H, L;
    split4(yx, yy, yz, yw, H, L);
    ((uint2*)(g_att_h + (size_t)row * CDIM))[tid] = H;
    ((uint2*)(g_att_l + (size_t)row * CDIM))[tid] = L;
}

// ================= launch =================
extern "C" void kernel_launch(void* const* d_in, const int* in_sizes, int n_in,
                              void* d_out, int out_size)
{
    const float* x     = (const float*)d_in[0];
    const float* enc   = (const float*)d_in[1];
    const float* W_enc = (const float*)d_in[2];
    const float* b_enc = (const float*)d_in[3];
    const float* ln1g  = (const float*)d_in[4];
    const float* ln1b  = (const float*)d_in[5];
    const float* ln2g  = (const float*)d_in[6];
    const float* ln2b  = (const float*)d_in[7];
    const float* W0    = (const float*)d_in[8];
    const float* W1    = (const float*)d_in[9];
    const float* Wa    = (const float*)d_in[10];
    float* out = (float*)d_out;

    static int attr_done = 0;
    if (!attr_done) {
        cudaFuncSetAttribute(gemm_mma, cudaFuncAttributeMaxDynamicSharedMemorySize, SMEM_GEMM_TOTAL);
        attr_done = 1;
    }

    void *p_xe, *p_h;
    cudaGetSymbolAddress(&p_xe,  g_xe);
    cudaGetSymbolAddress(&p_h,   g_h);
    float* xe  = (float*)p_xe;
    float* h   = (float*)p_h;

    void *p_ench, *p_encl, *p_wench, *p_wencl, *p_xnh, *p_xnl, *p_atth, *p_attl;
    void *p_w0h, *p_w0l, *p_w1h, *p_w1l;
    cudaGetSymbolAddress(&p_ench,  g_enc_h);  cudaGetSymbolAddress(&p_encl,  g_enc_l);
    cudaGetSymbolAddress(&p_wench, g_wenc_h); cudaGetSymbolAddress(&p_wencl, g_wenc_l);
    cudaGetSymbolAddress(&p_xnh,   g_xn_h);   cudaGetSymbolAddress(&p_xnl,   g_xn_l);
    cudaGetSymbolAddress(&p_atth,  g_att_h);  cudaGetSymbolAddress(&p_attl,  g_att_l);
    cudaGetSymbolAddress(&p_w0h,   g_w0_h);   cudaGetSymbolAddress(&p_w0l,   g_w0_l);
    cudaGetSymbolAddress(&p_w1h,   g_w1_h);   cudaGetSymbolAddress(&p_w1l,   g_w1_l);
    __nv_bfloat16* ench  = (__nv_bfloat16*)p_ench;  __nv_bfloat16* encl  = (__nv_bfloat16*)p_encl;
    __nv_bfloat16* wench = (__nv_bfloat16*)p_wench; __nv_bfloat16* wencl = (__nv_bfloat16*)p_wencl;
    __nv_bfloat16* xnh   = (__nv_bfloat16*)p_xnh;   __nv_bfloat16* xnl   = (__nv_bfloat16*)p_xnl;
    __nv_bfloat16* atth  = (__nv_bfloat16*)p_atth;  __nv_bfloat16* attl  = (__nv_bfloat16*)p_attl;
    __nv_bfloat16* w0h   = (__nv_bfloat16*)p_w0h;   __nv_bfloat16* w0l   = (__nv_bfloat16*)p_w0l;
    __nv_bfloat16* w1h   = (__nv_bfloat16*)p_w1h;   __nv_bfloat16* w1l   = (__nv_bfloat16*)p_w1l;

    dim3 ggrid(CDIM / 128, NROWS / 128);   // (4, 64)
    dim3 scan_grid(CDIM / 128, NCHUNK);

    // conversions of raw inputs
    convert_kernel<<<(NROWS * EDIM / 4 + 255) / 256, 256>>>(enc, ench, encl, NROWS * EDIM / 4);
    convert_kernel<<<(CDIM * EDIM / 4 + 255) / 256, 256>>>(W_enc, wench, wencl, CDIM * EDIM / 4);
    convert_kernel<<<(2 * CDIM * CDIM / 4 + 255) / 256, 256>>>(W0, w0h, w0l, 2 * CDIM * CDIM / 4);
    convert_kernel<<<(2 * CDIM * CDIM / 4 + 255) / 256, 256>>>(W1, w1h, w1l, 2 * CDIM * CDIM / 4);

    // 1) xe = x + enc @ W_enc^T + b_enc
    gemm_mma<<<ggrid, 256, SMEM_GEMM_TOTAL>>>(ench, encl, wench, wencl, xe,
                                              NROWS, CDIM, EDIM, 1, x, b_enc, 1.f);
    // 2) xn = LN1(xe), emitted directly as bf16 hi/lo
    ln_kernel<<<NROWS, 128>>>(xe, xnh, xnl, ln1g, ln1b);

    for (int head = 0; head < 2; head++) {
        const __nv_bfloat16* W0hh = w0h + (size_t)head * CDIM * CDIM;
        const __nv_bfloat16* W0hl = w0l + (size_t)head * CDIM * CDIM;
        const __nv_bfloat16* W1hh = w1h + (size_t)head * CDIM * CDIM;
        const __nv_bfloat16* W1hl = w1l + (size_t)head * CDIM * CDIM;
        const float* Wah = Wa + (size_t)head * 2 * CDIM;

        // 3) h = xn @ W0h^T
        gemm_mma<<<ggrid, 256, SMEM_GEMM_TOTAL>>>(xnh, xnl, W0hh, W0hl, h,
                                                  NROWS, CDIM, CDIM, 0, nullptr, nullptr, 1.f);
        // 4) s1, s2
        s_kernel<<<NROWS / 8, dim3(32, 8)>>>(h, Wah);
        // 5) rank + exp weights
        rank_kernel<<<NROWS / 256, 256>>>();
        // 6) chunked scans
        chunk_sum_kernel<<<scan_grid, 128>>>();
        chunk_scan_kernel<<<1, 512>>>();
        scan_write_kernel<<<scan_grid, 128>>>();
        // 7) combine + residual + LN2, emitted directly as bf16 hi/lo
        combine_kernel<<<NROWS, 128>>>(ln2g, ln2b);
        // 8) out (+)= elu(att @ W1h^T) / 2
        gemm_mma<<<ggrid, 256, SMEM_GEMM_TOTAL>>>(atth, attl, W1hh, W1hl, out,
                                                  NROWS, CDIM, CDIM, head == 0 ? 2 : 3,
                                                  nullptr, nullptr, 0.5f);
    }
}

// round 6
// speedup vs baseline: 7.8858x; 1.1085x over previous
#include <cuda_runtime.h>
#include <cuda_fp16.h>
#include <math.h>
#include <stdint.h>

#define NROWS 8192
#define CDIM  512
#define EDIM  256
#define HDIM  1024               // both heads' h concatenated
#define CHUNK 128
#define NCHUNK (NROWS / CHUNK)   // 64

// ================= helpers =================
__device__ __forceinline__ uint32_t smem_u32(const void* p) {
    uint32_t a;
    asm("{ .reg .u64 t; cvta.to.shared.u64 t, %1; cvt.u32.u64 %0, t; }" : "=r"(a) : "l"(p));
    return a;
}
#define CP_ASYNC(dst, src) \
    asm volatile("cp.async.cg.shared.global [%0], [%1], 16;" :: "r"(dst), "l"(src) : "memory")
#define CP_COMMIT() asm volatile("cp.async.commit_group;" ::: "memory")
#define CP_WAIT1()  asm volatile("cp.async.wait_group 1;" ::: "memory")
#define CP_WAIT0()  asm volatile("cp.async.wait_group 0;" ::: "memory")

#define LDMX4(r0, r1, r2, r3, a) \
    asm volatile("ldmatrix.sync.aligned.m8n8.x4.shared.b16 {%0,%1,%2,%3}, [%4];" \
        : "=r"(r0), "=r"(r1), "=r"(r2), "=r"(r3) : "r"(a))

#define MMA_F16(d, a, b0, b1) \
    asm volatile("mma.sync.aligned.m16n8k16.row.col.f32.f16.f16.f32 " \
        "{%0,%1,%2,%3}, {%4,%5,%6,%7}, {%8,%9}, {%0,%1,%2,%3};" \
        : "+f"((d)[0]), "+f"((d)[1]), "+f"((d)[2]), "+f"((d)[3]) \
        : "r"((a)[0]), "r"((a)[1]), "r"((a)[2]), "r"((a)[3]), "r"(b0), "r"(b1))

// pack 4 floats -> 4 fp16 hi + 4 fp16 lo
__device__ __forceinline__ void split4h(float x, float y, float z, float w,
                                        uint2& hi, uint2& lo)
{
    __half h0 = __float2half_rn(x);
    __half h1 = __float2half_rn(y);
    __half h2 = __float2half_rn(z);
    __half h3 = __float2half_rn(w);
    __half2 H0 = __halves2half2(h0, h1);
    __half2 H1 = __halves2half2(h2, h3);
    __half2 L0 = __halves2half2(__float2half_rn(x - __half2float(h0)),
                                __float2half_rn(y - __half2float(h1)));
    __half2 L1 = __halves2half2(__float2half_rn(z - __half2float(h2)),
                                __float2half_rn(w - __half2float(h3)));
    hi.x = *(uint32_t*)&H0; hi.y = *(uint32_t*)&H1;
    lo.x = *(uint32_t*)&L0; lo.y = *(uint32_t*)&L1;
}

// ================= scratch =================
__device__ float g_xe [NROWS * CDIM];
__device__ float g_h  [NROWS * HDIM];           // both heads
__device__ float g_s1 [NROWS];
__device__ float g_s2 [NROWS];
__device__ float g_sorted[NROWS];
__device__ int   g_perm  [NROWS];
__device__ float g_wpos  [NROWS];
__device__ float g_wneg  [NROWS];
__device__ float g_Apre[(NROWS + 1) * CDIM];
__device__ float g_Asuf[(NROWS + 1) * CDIM];
__device__ float g_Zpre[NROWS + 1];
__device__ float g_Zsuf[NROWS + 1];
__device__ float g_cpos[NCHUNK * CDIM];
__device__ float g_cneg[NCHUNK * CDIM];
__device__ float g_offp[NCHUNK * CDIM];
__device__ float g_offn[NCHUNK * CDIM];
__device__ float g_zcp[NCHUNK], g_zcn[NCHUNK];
__device__ float g_zoffp[NCHUNK], g_zoffn[NCHUNK];
// fp16 buffers: activations hi/lo, weights hi only
__device__ __half g_enc_h [NROWS * EDIM], g_enc_l [NROWS * EDIM];
__device__ __half g_wenc_h[CDIM * EDIM];
__device__ __half g_xn_h  [NROWS * CDIM], g_xn_l  [NROWS * CDIM];
__device__ __half g_att_h [NROWS * CDIM], g_att_l [NROWS * CDIM];
__device__ __half g_w0_h  [HDIM * CDIM];
__device__ __half g_w1_h  [2 * CDIM * CDIM];

// ================= fp32 -> fp16 conversions =================
__global__ __launch_bounds__(256)
void convert_full(const float* __restrict__ in,
                  __half* __restrict__ hi, __half* __restrict__ lo, int n4)
{
    int i = blockIdx.x * 256 + threadIdx.x;
    if (i >= n4) return;
    float4 v = ((const float4*)in)[i];
    uint2 H, L;
    split4h(v.x, v.y, v.z, v.w, H, L);
    ((uint2*)hi)[i] = H;
    ((uint2*)lo)[i] = L;
}

__global__ __launch_bounds__(256)
void convert_hi(const float* __restrict__ in, __half* __restrict__ hi, int n4)
{
    int i = blockIdx.x * 256 + threadIdx.x;
    if (i >= n4) return;
    float4 v = ((const float4*)in)[i];
    __half2 H0 = __halves2half2(__float2half_rn(v.x), __float2half_rn(v.y));
    __half2 H1 = __halves2half2(__float2half_rn(v.z), __float2half_rn(v.w));
    uint2 H; H.x = *(uint32_t*)&H0; H.y = *(uint32_t*)&H1;
    ((uint2*)hi)[i] = H;
}

// ================= fp16 2-term GEMM =================
// C[M,N] = (Ahi+Alo)[M,K] @ Bhi[N,K]^T. CTA 128x128, K-panel 32, 3-stage pipeline.
// modes: 0: C=acc   1: C=acc+addmat+bias[n]   2: C=elu(acc)*scale   3: C+=elu(acc)*scale
#define PADB    80                   // padded row stride in bytes (40 fp16)
#define MAT_B   (128 * PADB)         // 10240 bytes
#define STAGE_B (3 * MAT_B)          // Ah, Al, Bh = 30720
#define NSTAGE  3
#define SMEM_GEMM_TOTAL (NSTAGE * STAGE_B)  // 92160

__global__ __launch_bounds__(256, 2)
void gemm_f16(const __half* __restrict__ Ahi, const __half* __restrict__ Alo,
              const __half* __restrict__ Bhi,
              float* __restrict__ Cmat, int M, int N, int K, int mode,
              const float* __restrict__ addmat, const float* __restrict__ bias, float scale)
{
    extern __shared__ char smem[];
    const uint32_t sb = smem_u32(smem);
    const int tid = threadIdx.x;
    const int lane = tid & 31;
    const int wid = tid >> 5;
    const int warp_m = wid & 1;     // 2 warps in M
    const int warp_n = wid >> 1;    // 4 warps in N
    const int bx = blockIdx.x;      // N tile
    const int by = blockIdx.y;      // M tile

    const int r0 = tid >> 2,         c0 = tid & 3;
    const int r1 = (tid + 256) >> 2, c1 = tid & 3;

    const size_t a_g0 = (size_t)(by * 128 + r0) * K + c0 * 8;
    const size_t a_g1 = (size_t)(by * 128 + r1) * K + c1 * 8;
    const size_t b_g0 = (size_t)(bx * 128 + r0) * K + c0 * 8;
    const size_t b_g1 = (size_t)(bx * 128 + r1) * K + c1 * 8;
    const uint32_t s_o0 = r0 * PADB + c0 * 16;
    const uint32_t s_o1 = r1 * PADB + c1 * 16;

    const int NP = K >> 5;

#define ISSUE_STAGE(s) do { \
    const uint32_t _st = sb + (uint32_t)((s) % NSTAGE) * STAGE_B; \
    const size_t _ko = (size_t)(s) * 32; \
    CP_ASYNC(_st + s_o0,             Ahi + a_g0 + _ko); \
    CP_ASYNC(_st + s_o1,             Ahi + a_g1 + _ko); \
    CP_ASYNC(_st + MAT_B + s_o0,     Alo + a_g0 + _ko); \
    CP_ASYNC(_st + MAT_B + s_o1,     Alo + a_g1 + _ko); \
    CP_ASYNC(_st + 2 * MAT_B + s_o0, Bhi + b_g0 + _ko); \
    CP_ASYNC(_st + 2 * MAT_B + s_o1, Bhi + b_g1 + _ko); \
    CP_COMMIT(); \
} while (0)

    ISSUE_STAGE(0);
    if (NP > 1) ISSUE_STAGE(1);

    float acc[4][4][4];
#pragma unroll
    for (int i = 0; i < 4; i++)
#pragma unroll
        for (int j = 0; j < 4; j++)
#pragma unroll
            for (int q = 0; q < 4; q++) acc[i][j][q] = 0.f;

    const int lr = lane & 7, lsub = lane >> 3;
    const int a_moff = (lsub & 1) * 8 + lr;
    const int a_ksub = lsub >> 1;
    const int b_noff = (lsub >> 1) * 8 + lr;
    const int b_ksub = lsub & 1;

    for (int i = 0; i < NP; i++) {
        if (i + 1 < NP) CP_WAIT1(); else CP_WAIT0();
        __syncthreads();
        if (i + 2 < NP) ISSUE_STAGE(i + 2);

        const uint32_t st = sb + (uint32_t)(i % NSTAGE) * STAGE_B;
#pragma unroll
        for (int ks = 0; ks < 2; ks++) {
            const int kc = ks * 2;
            uint32_t bh[2][4];
#pragma unroll
            for (int p = 0; p < 2; p++) {
                uint32_t addr = st + 2 * MAT_B
                    + (uint32_t)(warp_n * 32 + p * 16 + b_noff) * PADB
                    + (uint32_t)(kc + b_ksub) * 16;
                LDMX4(bh[p][0], bh[p][1], bh[p][2], bh[p][3], addr);
            }
#pragma unroll
            for (int mi = 0; mi < 4; mi++) {
                uint32_t ah[4], al[4];
                uint32_t addr = st
                    + (uint32_t)(warp_m * 64 + mi * 16 + a_moff) * PADB
                    + (uint32_t)(kc + a_ksub) * 16;
                LDMX4(ah[0], ah[1], ah[2], ah[3], addr);
                LDMX4(al[0], al[1], al[2], al[3], addr + MAT_B);
#pragma unroll
                for (int p = 0; p < 2; p++) {
#pragma unroll
                    for (int q = 0; q < 2; q++) {
                        const int ni = p * 2 + q;
                        MMA_F16(acc[mi][ni], ah, bh[p][q * 2], bh[p][q * 2 + 1]);
                        MMA_F16(acc[mi][ni], al, bh[p][q * 2], bh[p][q * 2 + 1]);
                    }
                }
            }
        }
    }
#undef ISSUE_STAGE

    // ---- epilogue ----
    const int mbase = by * 128 + warp_m * 64 + (lane >> 2);
    const int nbase = bx * 128 + warp_n * 32 + (lane & 3) * 2;
#pragma unroll
    for (int mi = 0; mi < 4; mi++) {
#pragma unroll
        for (int ni = 0; ni < 4; ni++) {
            const int n = nbase + ni * 8;
#pragma unroll
            for (int half = 0; half < 2; half++) {
                const int m = mbase + mi * 16 + half * 8;
                float vx = acc[mi][ni][half * 2 + 0];
                float vy = acc[mi][ni][half * 2 + 1];
                const size_t idx = (size_t)m * N + n;
                if (mode == 1) {
                    float2 a = *(const float2*)(addmat + idx);
                    vx += a.x + bias[n];
                    vy += a.y + bias[n + 1];
                } else if (mode >= 2) {
                    vx = ((vx > 0.f) ? vx : expm1f(vx)) * scale;
                    vy = ((vy > 0.f) ? vy : expm1f(vy)) * scale;
                    if (mode == 3) {
                        float2 c = *(const float2*)(Cmat + idx);
                        vx += c.x; vy += c.y;
                    }
                }
                float2 o; o.x = vx; o.y = vy;
                *(float2*)(Cmat + idx) = o;
            }
        }
    }
}

// ================= row LayerNorm -> fp16 hi/lo =================
__global__ __launch_bounds__(128)
void ln_kernel(const float* __restrict__ in,
               __half* __restrict__ hi, __half* __restrict__ lo,
               const float* __restrict__ g, const float* __restrict__ b)
{
    const int row = blockIdx.x;
    const int tid = threadIdx.x;
    const int c = tid * 4;
    float4 v = *(const float4*)(in + (size_t)row * CDIM + c);
    float s  = v.x + v.y + v.z + v.w;
    float ss = v.x * v.x + v.y * v.y + v.z * v.z + v.w * v.w;
    __shared__ float rs[4], rss[4];
#pragma unroll
    for (int o = 16; o; o >>= 1) {
        s  += __shfl_down_sync(0xffffffffu, s,  o);
        ss += __shfl_down_sync(0xffffffffu, ss, o);
    }
    if ((tid & 31) == 0) { rs[tid >> 5] = s; rss[tid >> 5] = ss; }
    __syncthreads();
    float S  = rs[0] + rs[1] + rs[2] + rs[3];
    float SS = rss[0] + rss[1] + rss[2] + rss[3];
    float mu  = S * (1.f / CDIM);
    float var = SS * (1.f / CDIM) - mu * mu;
    float inv = rsqrtf(var + 1e-5f);
    float4 gv = *(const float4*)(g + c);
    float4 bv = *(const float4*)(b + c);
    float yx = (v.x - mu) * inv * gv.x + bv.x;
    float yy = (v.y - mu) * inv * gv.y + bv.y;
    float yz = (v.z - mu) * inv * gv.z + bv.z;
    float yw = (v.w - mu) * inv * gv.w + bv.w;
    uint2 H, L;
    split4h(yx, yy, yz, yw, H, L);
    ((uint2*)(hi + (size_t)row * CDIM))[tid] = H;
    ((uint2*)(lo + (size_t)row * CDIM))[tid] = L;
}

// ================= s1/s2 (h has row stride ldh) =================
__global__ void s_kernel(const float* __restrict__ h, const float* __restrict__ wa, int ldh)
{
    const int row = blockIdx.x * 8 + threadIdx.y;
    const int lane = threadIdx.x;
    const float* hr = h + (size_t)row * ldh;
    float a = 0.f, bv = 0.f;
#pragma unroll
    for (int t = 0; t < 16; t++) {
        int c = lane + 32 * t;
        float hv = hr[c];
        a  = fmaf(hv, wa[c], a);
        bv = fmaf(hv, wa[CDIM + c], bv);
    }
#pragma unroll
    for (int o = 16; o; o >>= 1) {
        a  += __shfl_down_sync(0xffffffffu, a,  o);
        bv += __shfl_down_sync(0xffffffffu, bv, o);
    }
    if (lane == 0) { g_s1[row] = a; g_s2[row] = bv; }
}

// ================= rank (sort by counting) =================
__global__ __launch_bounds__(256)
void rank_kernel()
{
    __shared__ float4 sh[NROWS / 4];
    for (int t = threadIdx.x; t < NROWS / 4; t += 256)
        sh[t] = ((const float4*)g_s2)[t];
    __syncthreads();
    const int i = blockIdx.x * 256 + threadIdx.x;
    const float v = g_s2[i];
    int r = 0;
#pragma unroll 4
    for (int jj = 0; jj < NROWS / 4; jj++) {
        float4 u = sh[jj];
        int j = jj * 4;
        r += (u.x < v) || (u.x == v && j + 0 < i);
        r += (u.y < v) || (u.y == v && j + 1 < i);
        r += (u.z < v) || (u.z == v && j + 2 < i);
        r += (u.w < v) || (u.w == v && j + 3 < i);
    }
    g_sorted[r] = v;
    g_perm[r]   = i;
    g_wpos[r]   = expf(v);
    g_wneg[r]   = expf(0.01f * v);
}

// ================= chunked scan: phase 1 =================
__global__ __launch_bounds__(128)
void chunk_sum_kernel(const float* __restrict__ hbase, int ldh)
{
    const int s = blockIdx.x, c = blockIdx.y;
    const int col = s * 128 + threadIdx.x;
    const int u0 = c * CHUNK;
    float accp = 0.f, accn = 0.f;
    float zp = 0.f, zn = 0.f;
    const bool do_z = (s == 0 && threadIdx.x == 0);
#pragma unroll 4
    for (int t = 0; t < CHUNK; t++) {
        const int u = u0 + t;
        const int r = g_perm[u];
        const float wp = g_wpos[u], wn = g_wneg[u];
        const float hv = hbase[(size_t)r * ldh + col];
        accp = fmaf(wp, hv, accp);
        accn = fmaf(wn, hv, accn);
        if (do_z) { zp += wp; zn += wn; }
    }
    g_cpos[c * CDIM + col] = accp;
    g_cneg[c * CDIM + col] = accn;
    if (do_z) { g_zcp[c] = zp; g_zcn[c] = zn; }
}

// ================= chunked scan: phase 2 =================
__global__ __launch_bounds__(512)
void chunk_scan_kernel()
{
    const int col = threadIdx.x;
    float run = 0.f;
    for (int c = 0; c < NCHUNK; c++) {
        g_offn[c * CDIM + col] = run;
        run += g_cneg[c * CDIM + col];
    }
    run = 0.f;
    for (int c = NCHUNK - 1; c >= 0; c--) {
        g_offp[c * CDIM + col] = run;
        run += g_cpos[c * CDIM + col];
    }
    if (col == 0) {
        float zr = 0.f;
        for (int c = 0; c < NCHUNK; c++) { g_zoffn[c] = zr; zr += g_zcn[c]; }
    } else if (col == 1) {
        float zr = 0.f;
        for (int c = NCHUNK - 1; c >= 0; c--) { g_zoffp[c] = zr; zr += g_zcp[c]; }
    }
}

// ================= chunked scan: phase 3 =================
__global__ __launch_bounds__(128)
void scan_write_kernel(const float* __restrict__ hbase, int ldh)
{
    const int s = blockIdx.x, c = blockIdx.y;
    const int col = s * 128 + threadIdx.x;
    const int u0 = c * CHUNK;

    float accn    = g_offn[c * CDIM + col];
    const float base_suf = g_offp[c * CDIM + col] + g_cpos[c * CDIM + col];
    float pp = 0.f;

    const bool do_z = (s == 0 && threadIdx.x == 0);
    float zn = 0.f, zbs = 0.f, zpp = 0.f;
    if (do_z) { zn = g_zoffn[c]; zbs = g_zoffp[c] + g_zcp[c]; }

    if (c == 0) {
        g_Apre[col] = 0.f;
        if (do_z) g_Zpre[0] = 0.f;
    }
    if (c == NCHUNK - 1) {
        g_Asuf[(size_t)NROWS * CDIM + col] = 0.f;
        if (do_z) g_Zsuf[NROWS] = 0.f;
    }

#pragma unroll 4
    for (int t = 0; t < CHUNK; t++) {
        const int u = u0 + t;
        const int r = g_perm[u];
        const float wp = g_wpos[u], wn = g_wneg[u];
        const float hv = hbase[(size_t)r * ldh + col];
        g_Asuf[(size_t)u * CDIM + col] = base_suf - pp;
        pp   = fmaf(wp, hv, pp);
        accn = fmaf(wn, hv, accn);
        g_Apre[(size_t)(u + 1) * CDIM + col] = accn;
        if (do_z) {
            g_Zsuf[u] = zbs - zpp;
            zpp += wp;
            zn  += wn;
            g_Zpre[u + 1] = zn;
        }
    }
}

// ================= combine + residual + LN2 -> fp16 hi/lo =================
__global__ __launch_bounds__(128)
void combine_kernel(const float* __restrict__ ln2g, const float* __restrict__ ln2b)
{
    const int row = blockIdx.x;
    const int tid = threadIdx.x;
    __shared__ int sk;
    __shared__ float rs[4], rss[4];
    if (tid == 0) {
        float thr = -g_s1[row];
        int lo = 0, hi = NROWS;
        while (lo < hi) {
            int mid = (lo + hi) >> 1;
            if (g_sorted[mid] <= thr) lo = mid + 1; else hi = mid;
        }
        sk = lo;
    }
    __syncthreads();
    const int k = sk;
    const float s1v = g_s1[row];
    const float ap = expf(s1v);
    const float an = expf(0.01f * s1v);
    const float den = ap * g_Zsuf[k] + an * g_Zpre[k];
    const float inv_den = 1.f / den;

    const int c = tid * 4;
    float4 suf = *(const float4*)(g_Asuf + (size_t)k * CDIM + c);
    float4 pre = *(const float4*)(g_Apre + (size_t)k * CDIM + c);
    float4 xev = *(const float4*)(g_xe + (size_t)row * CDIM + c);
    float vx = (ap * suf.x + an * pre.x) * inv_den + xev.x;
    float vy = (ap * suf.y + an * pre.y) * inv_den + xev.y;
    float vz = (ap * suf.z + an * pre.z) * inv_den + xev.z;
    float vw = (ap * suf.w + an * pre.w) * inv_den + xev.w;

    float s  = vx + vy + vz + vw;
    float ss = vx * vx + vy * vy + vz * vz + vw * vw;
#pragma unroll
    for (int o = 16; o; o >>= 1) {
        s  += __shfl_down_sync(0xffffffffu, s,  o);
        ss += __shfl_down_sync(0xffffffffu, ss, o);
    }
    if ((tid & 31) == 0) { rs[tid >> 5] = s; rss[tid >> 5] = ss; }
    __syncthreads();
    float S  = rs[0] + rs[1] + rs[2] + rs[3];
    float SS = rss[0] + rss[1] + rss[2] + rss[3];
    float mu  = S * (1.f / CDIM);
    float var = SS * (1.f / CDIM) - mu * mu;
    float inv = rsqrtf(var + 1e-5f);
    float4 gv = *(const float4*)(ln2g + c);
    float4 bv = *(const float4*)(ln2b + c);
    float yx = (vx - mu) * inv * gv.x + bv.x;
    float yy = (vy - mu) * inv * gv.y + bv.y;
    float yz = (vz - mu) * inv * gv.z + bv.z;
    float yw = (vw - mu) * inv * gv.w + bv.w;
    uint2 H, L;
    split4h(yx, yy, yz, yw, H, L);
    ((uint2*)(g_att_h + (size_t)row * CDIM))[tid] = H;
    ((uint2*)(g_att_l + (size_t)row * CDIM))[tid] = L;
}

// ================= launch =================
extern "C" void kernel_launch(void* const* d_in, const int* in_sizes, int n_in,
                              void* d_out, int out_size)
{
    const float* x     = (const float*)d_in[0];
    const float* enc   = (const float*)d_in[1];
    const float* W_enc = (const float*)d_in[2];
    const float* b_enc = (const float*)d_in[3];
    const float* ln1g  = (const float*)d_in[4];
    const float* ln1b  = (const float*)d_in[5];
    const float* ln2g  = (const float*)d_in[6];
    const float* ln2b  = (const float*)d_in[7];
    const float* W0    = (const float*)d_in[8];
    const float* W1    = (const float*)d_in[9];
    const float* Wa    = (const float*)d_in[10];
    float* out = (float*)d_out;

    static int attr_done = 0;
    if (!attr_done) {
        cudaFuncSetAttribute(gemm_f16, cudaFuncAttributeMaxDynamicSharedMemorySize, SMEM_GEMM_TOTAL);
        attr_done = 1;
    }

    void *p_xe, *p_h;
    cudaGetSymbolAddress(&p_xe,  g_xe);
    cudaGetSymbolAddress(&p_h,   g_h);
    float* xe = (float*)p_xe;
    float* h  = (float*)p_h;

    void *p_ench, *p_encl, *p_wench, *p_xnh, *p_xnl, *p_atth, *p_attl, *p_w0h, *p_w1h;
    cudaGetSymbolAddress(&p_ench,  g_enc_h);  cudaGetSymbolAddress(&p_encl,  g_enc_l);
    cudaGetSymbolAddress(&p_wench, g_wenc_h);
    cudaGetSymbolAddress(&p_xnh,   g_xn_h);   cudaGetSymbolAddress(&p_xnl,   g_xn_l);
    cudaGetSymbolAddress(&p_atth,  g_att_h);  cudaGetSymbolAddress(&p_attl,  g_att_l);
    cudaGetSymbolAddress(&p_w0h,   g_w0_h);   cudaGetSymbolAddress(&p_w1h,   g_w1_h);
    __half* ench  = (__half*)p_ench;  __half* encl = (__half*)p_encl;
    __half* wench = (__half*)p_wench;
    __half* xnh   = (__half*)p_xnh;   __half* xnl  = (__half*)p_xnl;
    __half* atth  = (__half*)p_atth;  __half* attl = (__half*)p_attl;
    __half* w0h   = (__half*)p_w0h;   __half* w1h  = (__half*)p_w1h;

    dim3 ggrid (CDIM / 128, NROWS / 128);   // (4, 64)
    dim3 hggrid(HDIM / 128, NROWS / 128);   // (8, 64) merged heads
    dim3 scan_grid(CDIM / 128, NCHUNK);

    // conversions: activations full split, weights hi only
    convert_full<<<(NROWS * EDIM / 4 + 255) / 256, 256>>>(enc, ench, encl, NROWS * EDIM / 4);
    convert_hi<<<(CDIM * EDIM / 4 + 255) / 256, 256>>>(W_enc, wench, CDIM * EDIM / 4);
    convert_hi<<<(HDIM * CDIM / 4 + 255) / 256, 256>>>(W0, w0h, HDIM * CDIM / 4);
    convert_hi<<<(2 * CDIM * CDIM / 4 + 255) / 256, 256>>>(W1, w1h, 2 * CDIM * CDIM / 4);

    // 1) xe = x + enc @ W_enc^T + b_enc
    gemm_f16<<<ggrid, 256, SMEM_GEMM_TOTAL>>>(ench, encl, wench, xe,
                                              NROWS, CDIM, EDIM, 1, x, b_enc, 1.f);
    // 2) xn = LN1(xe) -> fp16 hi/lo
    ln_kernel<<<NROWS, 128>>>(xe, xnh, xnl, ln1g, ln1b);

    // 3) h_both = xn @ [W0_0; W0_1]^T   (merged heads, N=1024)
    gemm_f16<<<hggrid, 256, SMEM_GEMM_TOTAL>>>(xnh, xnl, w0h, h,
                                               NROWS, HDIM, CDIM, 0, nullptr, nullptr, 1.f);

    for (int head = 0; head < 2; head++) {
        const float* hhead = h + (size_t)head * CDIM;      // column block, row stride HDIM
        const __half* W1h  = w1h + (size_t)head * CDIM * CDIM;
        const float* Wah   = Wa + (size_t)head * 2 * CDIM;

        // 4) s1, s2
        s_kernel<<<NROWS / 8, dim3(32, 8)>>>(hhead, Wah, HDIM);
        // 5) rank + exp weights
        rank_kernel<<<NROWS / 256, 256>>>();
        // 6) chunked scans
        chunk_sum_kernel<<<scan_grid, 128>>>(hhead, HDIM);
        chunk_scan_kernel<<<1, 512>>>();
        scan_write_kernel<<<scan_grid, 128>>>(hhead, HDIM);
        // 7) combine + residual + LN2 -> fp16 hi/lo
        combine_kernel<<<NROWS, 128>>>(ln2g, ln2b);
        // 8) out (+)= elu(att @ W1h^T) / 2
        gemm_f16<<<ggrid, 256, SMEM_GEMM_TOTAL>>>(atth, attl, W1h, out,
                                                  NROWS, CDIM, CDIM, head == 0 ? 2 : 3,
                                                  nullptr, nullptr, 0.5f);
    }
}

// round 7
// speedup vs baseline: 12.6294x; 1.6015x over previous
#include <cuda_runtime.h>
#include <cuda_fp16.h>
#include <math.h>
#include <stdint.h>

#define NROWS 8192
#define CDIM  512
#define EDIM  256
#define HDIM  1024               // both heads' h concatenated
#define CHUNK 128
#define NCHUNK (NROWS / CHUNK)   // 64

// ================= helpers =================
__device__ __forceinline__ uint32_t smem_u32(const void* p) {
    uint32_t a;
    asm("{ .reg .u64 t; cvta.to.shared.u64 t, %1; cvt.u32.u64 %0, t; }" : "=r"(a) : "l"(p));
    return a;
}
#define CP_ASYNC(dst, src) \
    asm volatile("cp.async.cg.shared.global [%0], [%1], 16;" :: "r"(dst), "l"(src) : "memory")
#define CP_COMMIT() asm volatile("cp.async.commit_group;" ::: "memory")
#define CP_WAIT1()  asm volatile("cp.async.wait_group 1;" ::: "memory")
#define CP_WAIT0()  asm volatile("cp.async.wait_group 0;" ::: "memory")

#define LDMX4(r0, r1, r2, r3, a) \
    asm volatile("ldmatrix.sync.aligned.m8n8.x4.shared.b16 {%0,%1,%2,%3}, [%4];" \
        : "=r"(r0), "=r"(r1), "=r"(r2), "=r"(r3) : "r"(a))

#define MMA_F16(d, a, b0, b1) \
    asm volatile("mma.sync.aligned.m16n8k16.row.col.f32.f16.f16.f32 " \
        "{%0,%1,%2,%3}, {%4,%5,%6,%7}, {%8,%9}, {%0,%1,%2,%3};" \
        : "+f"((d)[0]), "+f"((d)[1]), "+f"((d)[2]), "+f"((d)[3]) \
        : "r"((a)[0]), "r"((a)[1]), "r"((a)[2]), "r"((a)[3]), "r"(b0), "r"(b1))

__device__ __forceinline__ void split4h(float x, float y, float z, float w,
                                        uint2& hi, uint2& lo)
{
    __half h0 = __float2half_rn(x);
    __half h1 = __float2half_rn(y);
    __half h2 = __float2half_rn(z);
    __half h3 = __float2half_rn(w);
    __half2 H0 = __halves2half2(h0, h1);
    __half2 H1 = __halves2half2(h2, h3);
    __half2 L0 = __halves2half2(__float2half_rn(x - __half2float(h0)),
                                __float2half_rn(y - __half2float(h1)));
    __half2 L1 = __halves2half2(__float2half_rn(z - __half2float(h2)),
                                __float2half_rn(w - __half2float(h3)));
    hi.x = *(uint32_t*)&H0; hi.y = *(uint32_t*)&H1;
    lo.x = *(uint32_t*)&L0; lo.y = *(uint32_t*)&L1;
}
__device__ __forceinline__ uint2 pack4h(float x, float y, float z, float w)
{
    __half2 H0 = __halves2half2(__float2half_rn(x), __float2half_rn(y));
    __half2 H1 = __halves2half2(__float2half_rn(z), __float2half_rn(w));
    uint2 H; H.x = *(uint32_t*)&H0; H.y = *(uint32_t*)&H1;
    return H;
}

// ================= scratch =================
__device__ float g_xe [NROWS * CDIM];
__device__ float g_h  [NROWS * HDIM];
__device__ float g_s1 [2][NROWS];
__device__ float g_s2 [2][NROWS];
__device__ float g_sorted[2][NROWS];
__device__ int   g_perm  [2][NROWS];
__device__ float g_wpos  [2][NROWS];
__device__ float g_wneg  [2][NROWS];
__device__ float g_Apre[2][(NROWS + 1) * CDIM];
__device__ float g_Asuf[2][(NROWS + 1) * CDIM];
__device__ float g_Zpre[2][NROWS + 1];
__device__ float g_Zsuf[2][NROWS + 1];
__device__ float g_cpos[2][NCHUNK * CDIM];
__device__ float g_cneg[2][NCHUNK * CDIM];
__device__ float g_offp[2][NCHUNK * CDIM];
__device__ float g_offn[2][NCHUNK * CDIM];
__device__ float g_zcp[2][NCHUNK], g_zcn[2][NCHUNK];
__device__ float g_zoffp[2][NCHUNK], g_zoffn[2][NCHUNK];
// fp16 buffers
__device__ __half g_enc_h [NROWS * EDIM], g_enc_l [NROWS * EDIM];
__device__ __half g_wenc_h[CDIM * EDIM];
__device__ __half g_xn_h  [NROWS * CDIM];
__device__ __half g_att_h [2][NROWS * CDIM];
__device__ __half g_w0_h  [HDIM * CDIM];
__device__ __half g_w1_h  [2 * CDIM * CDIM];

// ================= conversions =================
__global__ __launch_bounds__(256)
void convert_full(const float* __restrict__ in,
                  __half* __restrict__ hi, __half* __restrict__ lo, int n4)
{
    int i = blockIdx.x * 256 + threadIdx.x;
    if (i >= n4) return;
    float4 v = ((const float4*)in)[i];
    uint2 H, L;
    split4h(v.x, v.y, v.z, v.w, H, L);
    ((uint2*)hi)[i] = H;
    ((uint2*)lo)[i] = L;
}

__global__ __launch_bounds__(256)
void convert_hi(const float* __restrict__ in, __half* __restrict__ hi, int n4)
{
    int i = blockIdx.x * 256 + threadIdx.x;
    if (i >= n4) return;
    float4 v = ((const float4*)in)[i];
    ((uint2*)hi)[i] = pack4h(v.x, v.y, v.z, v.w);
}

// ================= fp16 GEMM (templated on split terms) =================
// C[M,N] = (Ahi[+Alo])[M,K] @ Bhi[N,K]^T. CTA 128x128, K-panel 32, 3-stage.
// modes: 0: C=acc   1: C=acc+addmat+bias[n]   2: C=elu(acc)*scale   3: C+=elu(acc)*scale
#define PADB    80
#define MAT_B   (128 * PADB)         // 10240 bytes
#define NSTAGE  3

template<int USE_LO>
__global__ __launch_bounds__(256, 2)
void gemm_f16(const __half* __restrict__ Ahi, const __half* __restrict__ Alo,
              const __half* __restrict__ Bhi,
              float* __restrict__ Cmat, int M, int N, int K, int mode,
              const float* __restrict__ addmat, const float* __restrict__ bias, float scale)
{
    constexpr int NMAT = 2 + USE_LO;
    constexpr uint32_t STAGE_B = NMAT * MAT_B;
    constexpr uint32_t A_LO_OFF = 2 * MAT_B;     // only valid when USE_LO

    extern __shared__ char smem[];
    const uint32_t sb = smem_u32(smem);
    const int tid = threadIdx.x;
    const int lane = tid & 31;
    const int wid = tid >> 5;
    const int warp_m = wid & 1;
    const int warp_n = wid >> 1;
    const int bx = blockIdx.x;
    const int by = blockIdx.y;

    const int r0 = tid >> 2,         c0 = tid & 3;
    const int r1 = (tid + 256) >> 2, c1 = tid & 3;

    const size_t a_g0 = (size_t)(by * 128 + r0) * K + c0 * 8;
    const size_t a_g1 = (size_t)(by * 128 + r1) * K + c1 * 8;
    const size_t b_g0 = (size_t)(bx * 128 + r0) * K + c0 * 8;
    const size_t b_g1 = (size_t)(bx * 128 + r1) * K + c1 * 8;
    const uint32_t s_o0 = r0 * PADB + c0 * 16;
    const uint32_t s_o1 = r1 * PADB + c1 * 16;

    const int NP = K >> 5;

#define ISSUE_STAGE(s) do { \
    const uint32_t _st = sb + (uint32_t)((s) % NSTAGE) * STAGE_B; \
    const size_t _ko = (size_t)(s) * 32; \
    CP_ASYNC(_st + s_o0,         Ahi + a_g0 + _ko); \
    CP_ASYNC(_st + s_o1,         Ahi + a_g1 + _ko); \
    CP_ASYNC(_st + MAT_B + s_o0, Bhi + b_g0 + _ko); \
    CP_ASYNC(_st + MAT_B + s_o1, Bhi + b_g1 + _ko); \
    if (USE_LO) { \
        CP_ASYNC(_st + A_LO_OFF + s_o0, Alo + a_g0 + _ko); \
        CP_ASYNC(_st + A_LO_OFF + s_o1, Alo + a_g1 + _ko); \
    } \
    CP_COMMIT(); \
} while (0)

    ISSUE_STAGE(0);
    if (NP > 1) ISSUE_STAGE(1);

    float acc[4][4][4];
#pragma unroll
    for (int i = 0; i < 4; i++)
#pragma unroll
        for (int j = 0; j < 4; j++)
#pragma unroll
            for (int q = 0; q < 4; q++) acc[i][j][q] = 0.f;

    const int lr = lane & 7, lsub = lane >> 3;
    const int a_moff = (lsub & 1) * 8 + lr;
    const int a_ksub = lsub >> 1;
    const int b_noff = (lsub >> 1) * 8 + lr;
    const int b_ksub = lsub & 1;

    for (int i = 0; i < NP; i++) {
        if (i + 1 < NP) CP_WAIT1(); else CP_WAIT0();
        __syncthreads();
        if (i + 2 < NP) ISSUE_STAGE(i + 2);

        const uint32_t st = sb + (uint32_t)(i % NSTAGE) * STAGE_B;
#pragma unroll
        for (int ks = 0; ks < 2; ks++) {
            const int kc = ks * 2;
            uint32_t bh[2][4];
#pragma unroll
            for (int p = 0; p < 2; p++) {
                uint32_t addr = st + MAT_B
                    + (uint32_t)(warp_n * 32 + p * 16 + b_noff) * PADB
                    + (uint32_t)(kc + b_ksub) * 16;
                LDMX4(bh[p][0], bh[p][1], bh[p][2], bh[p][3], addr);
            }
#pragma unroll
            for (int mi = 0; mi < 4; mi++) {
                uint32_t ah[4];
                uint32_t addr = st
                    + (uint32_t)(warp_m * 64 + mi * 16 + a_moff) * PADB
                    + (uint32_t)(kc + a_ksub) * 16;
                LDMX4(ah[0], ah[1], ah[2], ah[3], addr);
                uint32_t al[4];
                if (USE_LO) { LDMX4(al[0], al[1], al[2], al[3], addr + A_LO_OFF); }
#pragma unroll
                for (int p = 0; p < 2; p++) {
#pragma unroll
                    for (int q = 0; q < 2; q++) {
                        const int ni = p * 2 + q;
                        MMA_F16(acc[mi][ni], ah, bh[p][q * 2], bh[p][q * 2 + 1]);
                        if (USE_LO) MMA_F16(acc[mi][ni], al, bh[p][q * 2], bh[p][q * 2 + 1]);
                    }
                }
            }
        }
    }
#undef ISSUE_STAGE

    // ---- epilogue ----
    const int mbase = by * 128 + warp_m * 64 + (lane >> 2);
    const int nbase = bx * 128 + warp_n * 32 + (lane & 3) * 2;
#pragma unroll
    for (int mi = 0; mi < 4; mi++) {
#pragma unroll
        for (int ni = 0; ni < 4; ni++) {
            const int n = nbase + ni * 8;
#pragma unroll
            for (int half = 0; half < 2; half++) {
                const int m = mbase + mi * 16 + half * 8;
                float vx = acc[mi][ni][half * 2 + 0];
                float vy = acc[mi][ni][half * 2 + 1];
                const size_t idx = (size_t)m * N + n;
                if (mode == 1) {
                    float2 a = *(const float2*)(addmat + idx);
                    vx += a.x + bias[n];
                    vy += a.y + bias[n + 1];
                } else if (mode >= 2) {
                    vx = ((vx > 0.f) ? vx : expm1f(vx)) * scale;
                    vy = ((vy > 0.f) ? vy : expm1f(vy)) * scale;
                    if (mode == 3) {
                        float2 c = *(const float2*)(Cmat + idx);
                        vx += c.x; vy += c.y;
                    }
                }
                float2 o; o.x = vx; o.y = vy;
                *(float2*)(Cmat + idx) = o;
            }
        }
    }
}

// ================= row LayerNorm -> fp16 hi =================
__global__ __launch_bounds__(128)
void ln_kernel(const float* __restrict__ in, __half* __restrict__ hi,
               const float* __restrict__ g, const float* __restrict__ b)
{
    const int row = blockIdx.x;
    const int tid = threadIdx.x;
    const int c = tid * 4;
    float4 v = *(const float4*)(in + (size_t)row * CDIM + c);
    float s  = v.x + v.y + v.z + v.w;
    float ss = v.x * v.x + v.y * v.y + v.z * v.z + v.w * v.w;
    __shared__ float rs[4], rss[4];
#pragma unroll
    for (int o = 16; o; o >>= 1) {
        s  += __shfl_down_sync(0xffffffffu, s,  o);
        ss += __shfl_down_sync(0xffffffffu, ss, o);
    }
    if ((tid & 31) == 0) { rs[tid >> 5] = s; rss[tid >> 5] = ss; }
    __syncthreads();
    float S  = rs[0] + rs[1] + rs[2] + rs[3];
    float SS = rss[0] + rss[1] + rss[2] + rss[3];
    float mu  = S * (1.f / CDIM);
    float var = SS * (1.f / CDIM) - mu * mu;
    float inv = rsqrtf(var + 1e-5f);
    float4 gv = *(const float4*)(g + c);
    float4 bv = *(const float4*)(b + c);
    ((uint2*)(hi + (size_t)row * CDIM))[tid] = pack4h(
        (v.x - mu) * inv * gv.x + bv.x,
        (v.y - mu) * inv * gv.y + bv.y,
        (v.z - mu) * inv * gv.z + bv.z,
        (v.w - mu) * inv * gv.w + bv.w);
}

// ================= s1/s2 (merged heads) =================
__global__ void s_kernel(const float* __restrict__ Wa)
{
    const int head = blockIdx.y;
    const int row = blockIdx.x * 8 + threadIdx.y;
    const int lane = threadIdx.x;
    const float* hr = g_h + (size_t)row * HDIM + head * CDIM;
    const float* wa = Wa + head * 2 * CDIM;
    float a = 0.f, bv = 0.f;
#pragma unroll
    for (int t = 0; t < 16; t++) {
        int c = lane + 32 * t;
        float hv = hr[c];
        a  = fmaf(hv, wa[c], a);
        bv = fmaf(hv, wa[CDIM + c], bv);
    }
#pragma unroll
    for (int o = 16; o; o >>= 1) {
        a  += __shfl_down_sync(0xffffffffu, a,  o);
        bv += __shfl_down_sync(0xffffffffu, bv, o);
    }
    if (lane == 0) { g_s1[head][row] = a; g_s2[head][row] = bv; }
}

// ================= rank (merged heads) =================
__global__ __launch_bounds__(256)
void rank_kernel()
{
    const int head = blockIdx.y;
    __shared__ float4 sh[NROWS / 4];
    for (int t = threadIdx.x; t < NROWS / 4; t += 256)
        sh[t] = ((const float4*)g_s2[head])[t];
    __syncthreads();
    const int i = blockIdx.x * 256 + threadIdx.x;
    const float v = g_s2[head][i];
    int r = 0;
#pragma unroll 4
    for (int jj = 0; jj < NROWS / 4; jj++) {
        float4 u = sh[jj];
        int j = jj * 4;
        r += (u.x < v) || (u.x == v && j + 0 < i);
        r += (u.y < v) || (u.y == v && j + 1 < i);
        r += (u.z < v) || (u.z == v && j + 2 < i);
        r += (u.w < v) || (u.w == v && j + 3 < i);
    }
    g_sorted[head][r] = v;
    g_perm[head][r]   = i;
    g_wpos[head][r]   = expf(v);
    g_wneg[head][r]   = expf(0.01f * v);
}

// ================= chunked scan: phase 1 (merged heads) =================
__global__ __launch_bounds__(128)
void chunk_sum_kernel()
{
    const int s = blockIdx.x, c = blockIdx.y, head = blockIdx.z;
    const int col = s * 128 + threadIdx.x;
    const int u0 = c * CHUNK;
    float accp = 0.f, accn = 0.f;
    float zp = 0.f, zn = 0.f;
    const bool do_z = (s == 0 && threadIdx.x == 0);
#pragma unroll 4
    for (int t = 0; t < CHUNK; t++) {
        const int u = u0 + t;
        const int r = g_perm[head][u];
        const float wp = g_wpos[head][u], wn = g_wneg[head][u];
        const float hv = g_h[(size_t)r * HDIM + head * CDIM + col];
        accp = fmaf(wp, hv, accp);
        accn = fmaf(wn, hv, accn);
        if (do_z) { zp += wp; zn += wn; }
    }
    g_cpos[head][c * CDIM + col] = accp;
    g_cneg[head][c * CDIM + col] = accn;
    if (do_z) { g_zcp[head][c] = zp; g_zcn[head][c] = zn; }
}

// ================= chunked scan: phase 2 (merged heads) =================
__global__ __launch_bounds__(512)
void chunk_scan_kernel()
{
    const int head = blockIdx.x;
    const int col = threadIdx.x;
    float run = 0.f;
    for (int c = 0; c < NCHUNK; c++) {
        g_offn[head][c * CDIM + col] = run;
        run += g_cneg[head][c * CDIM + col];
    }
    run = 0.f;
    for (int c = NCHUNK - 1; c >= 0; c--) {
        g_offp[head][c * CDIM + col] = run;
        run += g_cpos[head][c * CDIM + col];
    }
    if (col == 0) {
        float zr = 0.f;
        for (int c = 0; c < NCHUNK; c++) { g_zoffn[head][c] = zr; zr += g_zcn[head][c]; }
    } else if (col == 1) {
        float zr = 0.f;
        for (int c = NCHUNK - 1; c >= 0; c--) { g_zoffp[head][c] = zr; zr += g_zcp[head][c]; }
    }
}

// ================= chunked scan: phase 3 (merged heads) =================
__global__ __launch_bounds__(128)
void scan_write_kernel()
{
    const int s = blockIdx.x, c = blockIdx.y, head = blockIdx.z;
    const int col = s * 128 + threadIdx.x;
    const int u0 = c * CHUNK;

    float accn    = g_offn[head][c * CDIM + col];
    const float base_suf = g_offp[head][c * CDIM + col] + g_cpos[head][c * CDIM + col];
    float pp = 0.f;

    const bool do_z = (s == 0 && threadIdx.x == 0);
    float zn = 0.f, zbs = 0.f, zpp = 0.f;
    if (do_z) { zn = g_zoffn[head][c]; zbs = g_zoffp[head][c] + g_zcp[head][c]; }

    if (c == 0) {
        g_Apre[head][col] = 0.f;
        if (do_z) g_Zpre[head][0] = 0.f;
    }
    if (c == NCHUNK - 1) {
        g_Asuf[head][(size_t)NROWS * CDIM + col] = 0.f;
        if (do_z) g_Zsuf[head][NROWS] = 0.f;
    }

#pragma unroll 4
    for (int t = 0; t < CHUNK; t++) {
        const int u = u0 + t;
        const int r = g_perm[head][u];
        const float wp = g_wpos[head][u], wn = g_wneg[head][u];
        const float hv = g_h[(size_t)r * HDIM + head * CDIM + col];
        g_Asuf[head][(size_t)u * CDIM + col] = base_suf - pp;
        pp   = fmaf(wp, hv, pp);
        accn = fmaf(wn, hv, accn);
        g_Apre[head][(size_t)(u + 1) * CDIM + col] = accn;
        if (do_z) {
            g_Zsuf[head][u] = zbs - zpp;
            zpp += wp;
            zn  += wn;
            g_Zpre[head][u + 1] = zn;
        }
    }
}

// ================= combine + residual + LN2 -> fp16 hi (merged heads) ==========
__global__ __launch_bounds__(128)
void combine_kernel(const float* __restrict__ ln2g, const float* __restrict__ ln2b)
{
    const int head = blockIdx.y;
    const int row = blockIdx.x;
    const int tid = threadIdx.x;
    __shared__ int sk;
    __shared__ float rs[4], rss[4];
    if (tid == 0) {
        float thr = -g_s1[head][row];
        int lo = 0, hi = NROWS;
        while (lo < hi) {
            int mid = (lo + hi) >> 1;
            if (g_sorted[head][mid] <= thr) lo = mid + 1; else hi = mid;
        }
        sk = lo;
    }
    __syncthreads();
    const int k = sk;
    const float s1v = g_s1[head][row];
    const float ap = expf(s1v);
    const float an = expf(0.01f * s1v);
    const float den = ap * g_Zsuf[head][k] + an * g_Zpre[head][k];
    const float inv_den = 1.f / den;

    const int c = tid * 4;
    float4 suf = *(const float4*)(g_Asuf[head] + (size_t)k * CDIM + c);
    float4 pre = *(const float4*)(g_Apre[head] + (size_t)k * CDIM + c);
    float4 xev = *(const float4*)(g_xe + (size_t)row * CDIM + c);
    float vx = (ap * suf.x + an * pre.x) * inv_den + xev.x;
    float vy = (ap * suf.y + an * pre.y) * inv_den + xev.y;
    float vz = (ap * suf.z + an * pre.z) * inv_den + xev.z;
    float vw = (ap * suf.w + an * pre.w) * inv_den + xev.w;

    float s  = vx + vy + vz + vw;
    float ss = vx * vx + vy * vy + vz * vz + vw * vw;
#pragma unroll
    for (int o = 16; o; o >>= 1) {
        s  += __shfl_down_sync(0xffffffffu, s,  o);
        ss += __shfl_down_sync(0xffffffffu, ss, o);
    }
    if ((tid & 31) == 0) { rs[tid >> 5] = s; rss[tid >> 5] = ss; }
    __syncthreads();
    float S  = rs[0] + rs[1] + rs[2] + rs[3];
    float SS = rss[0] + rss[1] + rss[2] + rss[3];
    float mu  = S * (1.f / CDIM);
    float var = SS * (1.f / CDIM) - mu * mu;
    float inv = rsqrtf(var + 1e-5f);
    float4 gv = *(const float4*)(ln2g + c);
    float4 bv = *(const float4*)(ln2b + c);
    ((uint2*)(g_att_h[head] + (size_t)row * CDIM))[tid] = pack4h(
        (vx - mu) * inv * gv.x + bv.x,
        (vy - mu) * inv * gv.y + bv.y,
        (vz - mu) * inv * gv.z + bv.z,
        (vw - mu) * inv * gv.w + bv.w);
}

// ================= launch =================
extern "C" void kernel_launch(void* const* d_in, const int* in_sizes, int n_in,
                              void* d_out, int out_size)
{
    const float* x     = (const float*)d_in[0];
    const float* enc   = (const float*)d_in[1];
    const float* W_enc = (const float*)d_in[2];
    const float* b_enc = (const float*)d_in[3];
    const float* ln1g  = (const float*)d_in[4];
    const float* ln1b  = (const float*)d_in[5];
    const float* ln2g  = (const float*)d_in[6];
    const float* ln2b  = (const float*)d_in[7];
    const float* W0    = (const float*)d_in[8];
    const float* W1    = (const float*)d_in[9];
    const float* Wa    = (const float*)d_in[10];
    float* out = (float*)d_out;

    const int SMEM2 = NSTAGE * 2 * MAT_B;   // hi-only GEMM
    const int SMEM3 = NSTAGE * 3 * MAT_B;   // 2-term GEMM
    static int attr_done = 0;
    if (!attr_done) {
        cudaFuncSetAttribute(gemm_f16<0>, cudaFuncAttributeMaxDynamicSharedMemorySize, SMEM2);
        cudaFuncSetAttribute(gemm_f16<1>, cudaFuncAttributeMaxDynamicSharedMemorySize, SMEM3);
        attr_done = 1;
    }

    void *p_xe, *p_h;
    cudaGetSymbolAddress(&p_xe, g_xe);
    cudaGetSymbolAddress(&p_h,  g_h);
    float* xe = (float*)p_xe;
    float* h  = (float*)p_h;

    void *p_ench, *p_encl, *p_wench, *p_xnh, *p_atth, *p_w0h, *p_w1h;
    cudaGetSymbolAddress(&p_ench,  g_enc_h);
    cudaGetSymbolAddress(&p_encl,  g_enc_l);
    cudaGetSymbolAddress(&p_wench, g_wenc_h);
    cudaGetSymbolAddress(&p_xnh,   g_xn_h);
    cudaGetSymbolAddress(&p_atth,  g_att_h);
    cudaGetSymbolAddress(&p_w0h,   g_w0_h);
    cudaGetSymbolAddress(&p_w1h,   g_w1_h);
    __half* ench  = (__half*)p_ench;
    __half* encl  = (__half*)p_encl;
    __half* wench = (__half*)p_wench;
    __half* xnh   = (__half*)p_xnh;
    __half* atth  = (__half*)p_atth;      // [2][NROWS*CDIM]
    __half* w0h   = (__half*)p_w0h;
    __half* w1h   = (__half*)p_w1h;

    dim3 ggrid (CDIM / 128, NROWS / 128);   // (4, 64)
    dim3 hggrid(HDIM / 128, NROWS / 128);   // (8, 64)
    dim3 scan_grid(CDIM / 128, NCHUNK, 2);  // (4, 64, 2)

    // conversions
    convert_full<<<(NROWS * EDIM / 4 + 255) / 256, 256>>>(enc, ench, encl, NROWS * EDIM / 4);
    convert_hi<<<(CDIM * EDIM / 4 + 255) / 256, 256>>>(W_enc, wench, CDIM * EDIM / 4);
    convert_hi<<<(HDIM * CDIM / 4 + 255) / 256, 256>>>(W0, w0h, HDIM * CDIM / 4);
    convert_hi<<<(2 * CDIM * CDIM / 4 + 255) / 256, 256>>>(W1, w1h, 2 * CDIM * CDIM / 4);

    // 1) xe = x + enc @ W_enc^T + b_enc   (2-term: enc hi/lo)
    gemm_f16<1><<<ggrid, 256, SMEM3>>>(ench, encl, wench, xe,
                                       NROWS, CDIM, EDIM, 1, x, b_enc, 1.f);
    // 2) xn = LN1(xe) -> fp16 hi
    ln_kernel<<<NROWS, 128>>>(xe, xnh, ln1g, ln1b);

    // 3) h_both = xn @ [W0_0; W0_1]^T  (hi-only)
    gemm_f16<0><<<hggrid, 256, SMEM2>>>(xnh, nullptr, w0h, h,
                                        NROWS, HDIM, CDIM, 0, nullptr, nullptr, 1.f);

    // 4-7) merged per-head attention pipeline
    s_kernel<<<dim3(NROWS / 8, 2), dim3(32, 8)>>>(Wa);
    rank_kernel<<<dim3(NROWS / 256, 2), 256>>>();
    chunk_sum_kernel<<<scan_grid, 128>>>();
    chunk_scan_kernel<<<2, 512>>>();
    scan_write_kernel<<<scan_grid, 128>>>();
    combine_kernel<<<dim3(NROWS, 2), 128>>>(ln2g, ln2b);

    // 8) out = elu(att0 @ W1_0^T)/2 + elu(att1 @ W1_1^T)/2  (hi-only)
    gemm_f16<0><<<ggrid, 256, SMEM2>>>(atth, nullptr, w1h, out,
                                       NROWS, CDIM, CDIM, 2, nullptr, nullptr, 0.5f);
    gemm_f16<0><<<ggrid, 256, SMEM2>>>(atth + (size_t)NROWS * CDIM, nullptr,
                                       w1h + (size_t)CDIM * CDIM, out,
                                       NROWS, CDIM, CDIM, 3, nullptr, nullptr, 0.5f);
}

// round 8
// speedup vs baseline: 13.3545x; 1.0574x over previous
#include <cuda_runtime.h>
#include <cuda_fp16.h>
#include <math.h>
#include <stdint.h>

#define NROWS 8192
#define CDIM  512
#define EDIM  256
#define HDIM  1024               // both heads' h concatenated
#define CHUNK 128
#define NCHUNK (NROWS / CHUNK)   // 64

// ================= helpers =================
__device__ __forceinline__ uint32_t smem_u32(const void* p) {
    uint32_t a;
    asm("{ .reg .u64 t; cvta.to.shared.u64 t, %1; cvt.u32.u64 %0, t; }" : "=r"(a) : "l"(p));
    return a;
}
#define CP_ASYNC(dst, src) \
    asm volatile("cp.async.cg.shared.global [%0], [%1], 16;" :: "r"(dst), "l"(src) : "memory")
#define CP_COMMIT() asm volatile("cp.async.commit_group;" ::: "memory")
#define CP_WAIT1()  asm volatile("cp.async.wait_group 1;" ::: "memory")
#define CP_WAIT0()  asm volatile("cp.async.wait_group 0;" ::: "memory")

#define LDMX4(r0, r1, r2, r3, a) \
    asm volatile("ldmatrix.sync.aligned.m8n8.x4.shared.b16 {%0,%1,%2,%3}, [%4];" \
        : "=r"(r0), "=r"(r1), "=r"(r2), "=r"(r3) : "r"(a))

#define MMA_F16(d, a, b0, b1) \
    asm volatile("mma.sync.aligned.m16n8k16.row.col.f32.f16.f16.f32 " \
        "{%0,%1,%2,%3}, {%4,%5,%6,%7}, {%8,%9}, {%0,%1,%2,%3};" \
        : "+f"((d)[0]), "+f"((d)[1]), "+f"((d)[2]), "+f"((d)[3]) \
        : "r"((a)[0]), "r"((a)[1]), "r"((a)[2]), "r"((a)[3]), "r"(b0), "r"(b1))

__device__ __forceinline__ uint2 pack4h(float x, float y, float z, float w)
{
    __half2 H0 = __halves2half2(__float2half_rn(x), __float2half_rn(y));
    __half2 H1 = __halves2half2(__float2half_rn(z), __float2half_rn(w));
    uint2 H; H.x = *(uint32_t*)&H0; H.y = *(uint32_t*)&H1;
    return H;
}

// ================= scratch =================
__device__ float g_xe [NROWS * CDIM];
__device__ float g_h  [NROWS * HDIM];
__device__ float g_s1 [2][NROWS];
__device__ float g_s2 [2][NROWS];
__device__ float g_sorted[2][NROWS];
__device__ int   g_perm  [2][NROWS];
__device__ float g_wpos  [2][NROWS];
__device__ float g_wneg  [2][NROWS];
__device__ float g_Apre[2][(NROWS + 1) * CDIM];
__device__ float g_Asuf[2][(NROWS + 1) * CDIM];
__device__ float g_Zpre[2][NROWS + 1];
__device__ float g_Zsuf[2][NROWS + 1];
__device__ float g_cpos[2][NCHUNK * CDIM];
__device__ float g_cneg[2][NCHUNK * CDIM];
__device__ float g_offp[2][NCHUNK * CDIM];
__device__ float g_offn[2][NCHUNK * CDIM];
__device__ float g_zcp[2][NCHUNK], g_zcn[2][NCHUNK];
__device__ float g_zoffp[2][NCHUNK], g_zoffn[2][NCHUNK];
// fp16 buffers (hi only everywhere)
__device__ __half g_enc_h [NROWS * EDIM];
__device__ __half g_wenc_h[CDIM * EDIM];
__device__ __half g_xn_h  [NROWS * CDIM];
__device__ __half g_att_h [2][NROWS * CDIM];
__device__ __half g_w0_h  [HDIM * CDIM];
__device__ __half g_w1_h  [2 * CDIM * CDIM];

// ================= merged conversion (all 4 inputs in one launch) =============
#define N4_ENC  (NROWS * EDIM / 4)     // 524288
#define N4_WENC (CDIM * EDIM / 4)      // 32768
#define N4_W0   (HDIM * CDIM / 4)      // 131072
#define N4_W1   (2 * CDIM * CDIM / 4)  // 131072
#define N4_ALL  (N4_ENC + N4_WENC + N4_W0 + N4_W1)

__global__ __launch_bounds__(256)
void convert_all(const float* __restrict__ enc, const float* __restrict__ wenc,
                 const float* __restrict__ w0, const float* __restrict__ w1)
{
    int i = blockIdx.x * 256 + threadIdx.x;
    if (i >= N4_ALL) return;
    const float* src;
    __half* dst;
    int off;
    if (i < N4_ENC) {
        src = enc; dst = g_enc_h; off = i;
    } else if (i < N4_ENC + N4_WENC) {
        src = wenc; dst = g_wenc_h; off = i - N4_ENC;
    } else if (i < N4_ENC + N4_WENC + N4_W0) {
        src = w0; dst = g_w0_h; off = i - N4_ENC - N4_WENC;
    } else {
        src = w1; dst = g_w1_h; off = i - N4_ENC - N4_WENC - N4_W0;
    }
    float4 v = ((const float4*)src)[off];
    ((uint2*)dst)[off] = pack4h(v.x, v.y, v.z, v.w);
}

// ================= fp16 hi-only GEMM, K-panel 64, 3-stage =================
// C[M,N] = Ahi[M,K] @ Bhi[N,K]^T. CTA 128x128.
// modes: 0: C=acc   1: C=acc+addmat+bias[n]   2: C=elu(acc)*scale   3: C+=elu(acc)*scale
#define PADB    144                  // 64 halves = 128B + 16B pad
#define MAT_B   (128 * PADB)         // 18432 bytes
#define STAGE_B (2 * MAT_B)          // 36864
#define NSTAGE  3
#define SMEM_GEMM (NSTAGE * STAGE_B) // 110592

__global__ __launch_bounds__(256, 2)
void gemm_f16(const __half* __restrict__ Ahi, const __half* __restrict__ Bhi,
              float* __restrict__ Cmat, int M, int N, int K, int mode,
              const float* __restrict__ addmat, const float* __restrict__ bias, float scale)
{
    extern __shared__ char smem[];
    const uint32_t sb = smem_u32(smem);
    const int tid = threadIdx.x;
    const int lane = tid & 31;
    const int wid = tid >> 5;
    const int warp_m = wid & 1;
    const int warp_n = wid >> 1;
    const int bx = blockIdx.x;
    const int by = blockIdx.y;

    // loaders: per matrix per stage = 128 rows x 128B = 1024 chunks of 16B; 4/thread
    uint32_t s_off[4];
    size_t a_g[4], b_g[4];
#pragma unroll
    for (int j = 0; j < 4; j++) {
        const int idx = j * 256 + tid;
        const int row = idx >> 3, col = idx & 7;
        s_off[j] = row * PADB + col * 16;
        a_g[j] = (size_t)(by * 128 + row) * K + col * 8;
        b_g[j] = (size_t)(bx * 128 + row) * K + col * 8;
    }

    const int NP = K >> 6;

#define ISSUE_STAGE(s) do { \
    const uint32_t _st = sb + (uint32_t)((s) % NSTAGE) * STAGE_B; \
    const size_t _ko = (size_t)(s) * 64; \
    _Pragma("unroll") \
    for (int j = 0; j < 4; j++) { \
        CP_ASYNC(_st + s_off[j],         Ahi + a_g[j] + _ko); \
        CP_ASYNC(_st + MAT_B + s_off[j], Bhi + b_g[j] + _ko); \
    } \
    CP_COMMIT(); \
} while (0)

    ISSUE_STAGE(0);
    if (NP > 1) ISSUE_STAGE(1);

    float acc[4][4][4];
#pragma unroll
    for (int i = 0; i < 4; i++)
#pragma unroll
        for (int j = 0; j < 4; j++)
#pragma unroll
            for (int q = 0; q < 4; q++) acc[i][j][q] = 0.f;

    const int lr = lane & 7, lsub = lane >> 3;
    const int a_moff = (lsub & 1) * 8 + lr;
    const int a_ksub = lsub >> 1;
    const int b_noff = (lsub >> 1) * 8 + lr;
    const int b_ksub = lsub & 1;

    for (int i = 0; i < NP; i++) {
        if (i + 1 < NP) CP_WAIT1(); else CP_WAIT0();
        __syncthreads();
        if (i + 2 < NP) ISSUE_STAGE(i + 2);

        const uint32_t st = sb + (uint32_t)(i % NSTAGE) * STAGE_B;
#pragma unroll
        for (int ks = 0; ks < 4; ks++) {          // four k16 steps per 64-panel
            const int kc = ks * 2;
            uint32_t bh[2][4];
#pragma unroll
            for (int p = 0; p < 2; p++) {
                uint32_t addr = st + MAT_B
                    + (uint32_t)(warp_n * 32 + p * 16 + b_noff) * PADB
                    + (uint32_t)(kc + b_ksub) * 16;
                LDMX4(bh[p][0], bh[p][1], bh[p][2], bh[p][3], addr);
            }
#pragma unroll
            for (int mi = 0; mi < 4; mi++) {
                uint32_t ah[4];
                uint32_t addr = st
                    + (uint32_t)(warp_m * 64 + mi * 16 + a_moff) * PADB
                    + (uint32_t)(kc + a_ksub) * 16;
                LDMX4(ah[0], ah[1], ah[2], ah[3], addr);
#pragma unroll
                for (int p = 0; p < 2; p++) {
#pragma unroll
                    for (int q = 0; q < 2; q++) {
                        MMA_F16(acc[mi][p * 2 + q], ah, bh[p][q * 2], bh[p][q * 2 + 1]);
                    }
                }
            }
        }
    }
#undef ISSUE_STAGE

    // ---- epilogue ----
    const int mbase = by * 128 + warp_m * 64 + (lane >> 2);
    const int nbase = bx * 128 + warp_n * 32 + (lane & 3) * 2;
#pragma unroll
    for (int mi = 0; mi < 4; mi++) {
#pragma unroll
        for (int ni = 0; ni < 4; ni++) {
            const int n = nbase + ni * 8;
#pragma unroll
            for (int half = 0; half < 2; half++) {
                const int m = mbase + mi * 16 + half * 8;
                float vx = acc[mi][ni][half * 2 + 0];
                float vy = acc[mi][ni][half * 2 + 1];
                const size_t idx = (size_t)m * N + n;
                if (mode == 1) {
                    float2 a = *(const float2*)(addmat + idx);
                    vx += a.x + bias[n];
                    vy += a.y + bias[n + 1];
                } else if (mode >= 2) {
                    vx = ((vx > 0.f) ? vx : expm1f(vx)) * scale;
                    vy = ((vy > 0.f) ? vy : expm1f(vy)) * scale;
                    if (mode == 3) {
                        float2 c = *(const float2*)(Cmat + idx);
                        vx += c.x; vy += c.y;
                    }
                }
                float2 o; o.x = vx; o.y = vy;
                *(float2*)(Cmat + idx) = o;
            }
        }
    }
}

// ================= row LayerNorm -> fp16 hi =================
__global__ __launch_bounds__(128)
void ln_kernel(const float* __restrict__ in, __half* __restrict__ hi,
               const float* __restrict__ g, const float* __restrict__ b)
{
    const int row = blockIdx.x;
    const int tid = threadIdx.x;
    const int c = tid * 4;
    float4 v = *(const float4*)(in + (size_t)row * CDIM + c);
    float s  = v.x + v.y + v.z + v.w;
    float ss = v.x * v.x + v.y * v.y + v.z * v.z + v.w * v.w;
    __shared__ float rs[4], rss[4];
#pragma unroll
    for (int o = 16; o; o >>= 1) {
        s  += __shfl_down_sync(0xffffffffu, s,  o);
        ss += __shfl_down_sync(0xffffffffu, ss, o);
    }
    if ((tid & 31) == 0) { rs[tid >> 5] = s; rss[tid >> 5] = ss; }
    __syncthreads();
    float S  = rs[0] + rs[1] + rs[2] + rs[3];
    float SS = rss[0] + rss[1] + rss[2] + rss[3];
    float mu  = S * (1.f / CDIM);
    float var = SS * (1.f / CDIM) - mu * mu;
    float inv = rsqrtf(var + 1e-5f);
    float4 gv = *(const float4*)(g + c);
    float4 bv = *(const float4*)(b + c);
    ((uint2*)(hi + (size_t)row * CDIM))[tid] = pack4h(
        (v.x - mu) * inv * gv.x + bv.x,
        (v.y - mu) * inv * gv.y + bv.y,
        (v.z - mu) * inv * gv.z + bv.z,
        (v.w - mu) * inv * gv.w + bv.w);
}

// ================= s1/s2 (merged heads) =================
__global__ void s_kernel(const float* __restrict__ Wa)
{
    const int head = blockIdx.y;
    const int row = blockIdx.x * 8 + threadIdx.y;
    const int lane = threadIdx.x;
    const float* hr = g_h + (size_t)row * HDIM + head * CDIM;
    const float* wa = Wa + head * 2 * CDIM;
    float a = 0.f, bv = 0.f;
#pragma unroll
    for (int t = 0; t < 16; t++) {
        int c = lane + 32 * t;
        float hv = hr[c];
        a  = fmaf(hv, wa[c], a);
        bv = fmaf(hv, wa[CDIM + c], bv);
    }
#pragma unroll
    for (int o = 16; o; o >>= 1) {
        a  += __shfl_down_sync(0xffffffffu, a,  o);
        bv += __shfl_down_sync(0xffffffffu, bv, o);
    }
    if (lane == 0) { g_s1[head][row] = a; g_s2[head][row] = bv; }
}

// ================= rank (merged heads) =================
__global__ __launch_bounds__(256)
void rank_kernel()
{
    const int head = blockIdx.y;
    __shared__ float4 sh[NROWS / 4];
    for (int t = threadIdx.x; t < NROWS / 4; t += 256)
        sh[t] = ((const float4*)g_s2[head])[t];
    __syncthreads();
    const int i = blockIdx.x * 256 + threadIdx.x;
    const float v = g_s2[head][i];
    int r = 0;
#pragma unroll 4
    for (int jj = 0; jj < NROWS / 4; jj++) {
        float4 u = sh[jj];
        int j = jj * 4;
        r += (u.x < v) || (u.x == v && j + 0 < i);
        r += (u.y < v) || (u.y == v && j + 1 < i);
        r += (u.z < v) || (u.z == v && j + 2 < i);
        r += (u.w < v) || (u.w == v && j + 3 < i);
    }
    g_sorted[head][r] = v;
    g_perm[head][r]   = i;
    g_wpos[head][r]   = expf(v);
    g_wneg[head][r]   = expf(0.01f * v);
}

// ================= chunked scan: phase 1 (merged heads) =================
__global__ __launch_bounds__(128)
void chunk_sum_kernel()
{
    const int s = blockIdx.x, c = blockIdx.y, head = blockIdx.z;
    const int col = s * 128 + threadIdx.x;
    const int u0 = c * CHUNK;
    float accp = 0.f, accn = 0.f;
    float zp = 0.f, zn = 0.f;
    const bool do_z = (s == 0 && threadIdx.x == 0);
#pragma unroll 4
    for (int t = 0; t < CHUNK; t++) {
        const int u = u0 + t;
        const int r = g_perm[head][u];
        const float wp = g_wpos[head][u], wn = g_wneg[head][u];
        const float hv = g_h[(size_t)r * HDIM + head * CDIM + col];
        accp = fmaf(wp, hv, accp);
        accn = fmaf(wn, hv, accn);
        if (do_z) { zp += wp; zn += wn; }
    }
    g_cpos[head][c * CDIM + col] = accp;
    g_cneg[head][c * CDIM + col] = accn;
    if (do_z) { g_zcp[head][c] = zp; g_zcn[head][c] = zn; }
}

// ================= chunked scan: phase 2 (merged heads) =================
__global__ __launch_bounds__(512)
void chunk_scan_kernel()
{
    const int head = blockIdx.x;
    const int col = threadIdx.x;
    float run = 0.f;
    for (int c = 0; c < NCHUNK; c++) {
        g_offn[head][c * CDIM + col] = run;
        run += g_cneg[head][c * CDIM + col];
    }
    run = 0.f;
    for (int c = NCHUNK - 1; c >= 0; c--) {
        g_offp[head][c * CDIM + col] = run;
        run += g_cpos[head][c * CDIM + col];
    }
    if (col == 0) {
        float zr = 0.f;
        for (int c = 0; c < NCHUNK; c++) { g_zoffn[head][c] = zr; zr += g_zcn[head][c]; }
    } else if (col == 1) {
        float zr = 0.f;
        for (int c = NCHUNK - 1; c >= 0; c--) { g_zoffp[head][c] = zr; zr += g_zcp[head][c]; }
    }
}

// ================= chunked scan: phase 3 (merged heads) =================
__global__ __launch_bounds__(128)
void scan_write_kernel()
{
    const int s = blockIdx.x, c = blockIdx.y, head = blockIdx.z;
    const int col = s * 128 + threadIdx.x;
    const int u0 = c * CHUNK;

    float accn    = g_offn[head][c * CDIM + col];
    const float base_suf = g_offp[head][c * CDIM + col] + g_cpos[head][c * CDIM + col];
    float pp = 0.f;

    const bool do_z = (s == 0 && threadIdx.x == 0);
    float zn = 0.f, zbs = 0.f, zpp = 0.f;
    if (do_z) { zn = g_zoffn[head][c]; zbs = g_zoffp[head][c] + g_zcp[head][c]; }

    if (c == 0) {
        g_Apre[head][col] = 0.f;
        if (do_z) g_Zpre[head][0] = 0.f;
    }
    if (c == NCHUNK - 1) {
        g_Asuf[head][(size_t)NROWS * CDIM + col] = 0.f;
        if (do_z) g_Zsuf[head][NROWS] = 0.f;
    }

#pragma unroll 4
    for (int t = 0; t < CHUNK; t++) {
        const int u = u0 + t;
        const int r = g_perm[head][u];
        const float wp = g_wpos[head][u], wn = g_wneg[head][u];
        const float hv = g_h[(size_t)r * HDIM + head * CDIM + col];
        g_Asuf[head][(size_t)u * CDIM + col] = base_suf - pp;
        pp   = fmaf(wp, hv, pp);
        accn = fmaf(wn, hv, accn);
        g_Apre[head][(size_t)(u + 1) * CDIM + col] = accn;
        if (do_z) {
            g_Zsuf[head][u] = zbs - zpp;
            zpp += wp;
            zn  += wn;
            g_Zpre[head][u + 1] = zn;
        }
    }
}

// ================= combine + residual + LN2 -> fp16 hi (merged heads) ==========
__global__ __launch_bounds__(128)
void combine_kernel(const float* __restrict__ ln2g, const float* __restrict__ ln2b)
{
    const int head = blockIdx.y;
    const int row = blockIdx.x;
    const int tid = threadIdx.x;
    __shared__ int sk;
    __shared__ float rs[4], rss[4];
    if (tid == 0) {
        float thr = -g_s1[head][row];
        int lo = 0, hi = NROWS;
        while (lo < hi) {
            int mid = (lo + hi) >> 1;
            if (g_sorted[head][mid] <= thr) lo = mid + 1; else hi = mid;
        }
        sk = lo;
    }
    __syncthreads();
    const int k = sk;
    const float s1v = g_s1[head][row];
    const float ap = expf(s1v);
    const float an = expf(0.01f * s1v);
    const float den = ap * g_Zsuf[head][k] + an * g_Zpre[head][k];
    const float inv_den = 1.f / den;

    const int c = tid * 4;
    float4 suf = *(const float4*)(g_Asuf[head] + (size_t)k * CDIM + c);
    float4 pre = *(const float4*)(g_Apre[head] + (size_t)k * CDIM + c);
    float4 xev = *(const float4*)(g_xe + (size_t)row * CDIM + c);
    float vx = (ap * suf.x + an * pre.x) * inv_den + xev.x;
    float vy = (ap * suf.y + an * pre.y) * inv_den + xev.y;
    float vz = (ap * suf.z + an * pre.z) * inv_den + xev.z;
    float vw = (ap * suf.w + an * pre.w) * inv_den + xev.w;

    float s  = vx + vy + vz + vw;
    float ss = vx * vx + vy * vy + vz * vz + vw * vw;
#pragma unroll
    for (int o = 16; o; o >>= 1) {
        s  += __shfl_down_sync(0xffffffffu, s,  o);
        ss += __shfl_down_sync(0xffffffffu, ss, o);
    }
    if ((tid & 31) == 0) { rs[tid >> 5] = s; rss[tid >> 5] = ss; }
    __syncthreads();
    float S  = rs[0] + rs[1] + rs[2] + rs[3];
    float SS = rss[0] + rss[1] + rss[2] + rss[3];
    float mu  = S * (1.f / CDIM);
    float var = SS * (1.f / CDIM) - mu * mu;
    float inv = rsqrtf(var + 1e-5f);
    float4 gv = *(const float4*)(ln2g + c);
    float4 bv = *(const float4*)(ln2b + c);
    ((uint2*)(g_att_h[head] + (size_t)row * CDIM))[tid] = pack4h(
        (vx - mu) * inv * gv.x + bv.x,
        (vy - mu) * inv * gv.y + bv.y,
        (vz - mu) * inv * gv.z + bv.z,
        (vw - mu) * inv * gv.w + bv.w);
}

// ================= launch =================
extern "C" void kernel_launch(void* const* d_in, const int* in_sizes, int n_in,
                              void* d_out, int out_size)
{
    const float* x     = (const float*)d_in[0];
    const float* enc   = (const float*)d_in[1];
    const float* W_enc = (const float*)d_in[2];
    const float* b_enc = (const float*)d_in[3];
    const float* ln1g  = (const float*)d_in[4];
    const float* ln1b  = (const float*)d_in[5];
    const float* ln2g  = (const float*)d_in[6];
    const float* ln2b  = (const float*)d_in[7];
    const float* W0    = (const float*)d_in[8];
    const float* W1    = (const float*)d_in[9];
    const float* Wa    = (const float*)d_in[10];
    float* out = (float*)d_out;

    static int attr_done = 0;
    if (!attr_done) {
        cudaFuncSetAttribute(gemm_f16, cudaFuncAttributeMaxDynamicSharedMemorySize, SMEM_GEMM);
        attr_done = 1;
    }

    void *p_xe, *p_h;
    cudaGetSymbolAddress(&p_xe, g_xe);
    cudaGetSymbolAddress(&p_h,  g_h);
    float* xe = (float*)p_xe;
    float* h  = (float*)p_h;

    void *p_ench, *p_wench, *p_xnh, *p_atth, *p_w0h, *p_w1h;
    cudaGetSymbolAddress(&p_ench,  g_enc_h);
    cudaGetSymbolAddress(&p_wench, g_wenc_h);
    cudaGetSymbolAddress(&p_xnh,   g_xn_h);
    cudaGetSymbolAddress(&p_atth,  g_att_h);
    cudaGetSymbolAddress(&p_w0h,   g_w0_h);
    cudaGetSymbolAddress(&p_w1h,   g_w1_h);
    __half* ench  = (__half*)p_ench;
    __half* wench = (__half*)p_wench;
    __half* xnh   = (__half*)p_xnh;
    __half* atth  = (__half*)p_atth;      // [2][NROWS*CDIM]
    __half* w0h   = (__half*)p_w0h;
    __half* w1h   = (__half*)p_w1h;

    dim3 ggrid (CDIM / 128, NROWS / 128);   // (4, 64)
    dim3 hggrid(HDIM / 128, NROWS / 128);   // (8, 64)
    dim3 scan_grid(CDIM / 128, NCHUNK, 2);  // (4, 64, 2)

    // all conversions in one launch
    convert_all<<<(N4_ALL + 255) / 256, 256>>>(enc, W_enc, W0, W1);

    // 1) xe = x + enc @ W_enc^T + b_enc   (hi-only)
    gemm_f16<<<ggrid, 256, SMEM_GEMM>>>(ench, wench, xe,
                                        NROWS, CDIM, EDIM, 1, x, b_enc, 1.f);
    // 2) xn = LN1(xe) -> fp16 hi
    ln_kernel<<<NROWS, 128>>>(xe, xnh, ln1g, ln1b);

    // 3) h_both = xn @ [W0_0; W0_1]^T
    gemm_f16<<<hggrid, 256, SMEM_GEMM>>>(xnh, w0h, h,
                                         NROWS, HDIM, CDIM, 0, nullptr, nullptr, 1.f);

    // 4-7) merged per-head attention pipeline
    s_kernel<<<dim3(NROWS / 8, 2), dim3(32, 8)>>>(Wa);
    rank_kernel<<<dim3(NROWS / 256, 2), 256>>>();
    chunk_sum_kernel<<<scan_grid, 128>>>();
    chunk_scan_kernel<<<2, 512>>>();
    scan_write_kernel<<<scan_grid, 128>>>();
    combine_kernel<<<dim3(NROWS, 2), 128>>>(ln2g, ln2b);

    // 8) out = elu(att0 @ W1_0^T)/2 + elu(att1 @ W1_1^T)/2
    gemm_f16<<<ggrid, 256, SMEM_GEMM>>>(atth, w1h, out,
                                        NROWS, CDIM, CDIM, 2, nullptr, nullptr, 0.5f);
    gemm_f16<<<ggrid, 256, SMEM_GEMM>>>(atth + (size_t)NROWS * CDIM,
                                        w1h + (size_t)CDIM * CDIM, out,
                                        NROWS, CDIM, CDIM, 3, nullptr, nullptr, 0.5f);
}